// round 1
// baseline (speedup 1.0000x reference)
#include <cuda_runtime.h>
#include <cuda_bf16.h>
#include <cstddef>

// ---------------- problem constants ----------------
#define U_  1024
#define B_  8
#define D_  512
#define H_  8
#define HD_ 64
#define CL_ 64
#define RC_ 4
#define C_  16
#define R_  64          // C_*RC_
#define S_  16          // C_
#define M_  15          // C_-1
#define Q_  1104        // R_+U_+S_
#define KV_ 1103        // M_+R_+U_
#define PE_ 2047        // 2U-1
#define NEG_INF_ (-100000000.0f)
#define SCALING_ 0.125f // HD^-0.5

// ---------------- scratch (device globals; no allocs) ----------------
__device__ float g_q[(size_t)Q_ * B_ * D_];            // 18 MB   [q][b][d]
__device__ float g_kv[(size_t)KV_ * B_ * 2 * D_];      // 36 MB   [k][b][2d]
__device__ float g_pos[(size_t)PE_ * D_];              // 4 MB    [p][d]
__device__ float g_scores[(size_t)B_ * H_ * Q_ * KV_]; // 312 MB  [bh][q][k]
__device__ float g_attn[(size_t)Q_ * B_ * D_];         // 18 MB   [q][b][d]

// ---------------- generic NT GEMM: C[i,j] = sum_k A[i,k]*B[j,k] (+bias) ----------------
__global__ void gemm_nt_kernel(const float* __restrict__ A, int lda,
                               const float* __restrict__ Bm, int ldb,
                               float* __restrict__ Cm, int ldc,
                               int Mr, int Nc, int Kd,
                               const float* __restrict__ bias)
{
    __shared__ float As[64][17];
    __shared__ float Bs[64][17];
    const int row0 = blockIdx.y * 64;
    const int col0 = blockIdx.x * 64;
    const int tid = threadIdx.x;
    const int ty = tid >> 4, tx = tid & 15;
    float acc[4][4] = {};
    for (int k0 = 0; k0 < Kd; k0 += 16) {
        #pragma unroll
        for (int i = 0; i < 4; i++) {
            int idx = tid + i * 256;
            int r = idx >> 4, kk = idx & 15;
            int gr = row0 + r;
            As[r][kk] = (gr < Mr) ? A[(size_t)gr * lda + k0 + kk] : 0.f;
            int gc = col0 + r;
            Bs[r][kk] = (gc < Nc) ? Bm[(size_t)gc * ldb + k0 + kk] : 0.f;
        }
        __syncthreads();
        #pragma unroll
        for (int kk = 0; kk < 16; kk++) {
            float av[4], bv[4];
            #pragma unroll
            for (int a = 0; a < 4; a++) av[a] = As[ty * 4 + a][kk];
            #pragma unroll
            for (int b2 = 0; b2 < 4; b2++) bv[b2] = Bs[tx * 4 + b2][kk];
            #pragma unroll
            for (int a = 0; a < 4; a++)
                #pragma unroll
                for (int b2 = 0; b2 < 4; b2++)
                    acc[a][b2] += av[a] * bv[b2];
        }
        __syncthreads();
    }
    #pragma unroll
    for (int a = 0; a < 4; a++) {
        int gr = row0 + ty * 4 + a;
        if (gr >= Mr) continue;
        #pragma unroll
        for (int b2 = 0; b2 < 4; b2++) {
            int gc = col0 + tx * 4 + b2;
            if (gc >= Nc) continue;
            float v = acc[a][b2];
            if (bias) v += bias[gc];
            Cm[(size_t)gr * ldc + gc] = v;
        }
    }
}

// ---------------- matrix_ac: scores[bh][q][k] = (q+pbu)·key ----------------
__global__ void attn_ac_kernel(const float* __restrict__ pbu)
{
    const int bh = blockIdx.z, b = bh >> 3, h = bh & 7;
    const int q0 = blockIdx.y * 64, c0 = blockIdx.x * 64;
    __shared__ float As[64][17];
    __shared__ float Bs[64][17];
    const float* qbase = g_q + (size_t)b * D_ + h * HD_;
    const float* kbase = g_kv + (size_t)b * 2 * D_ + h * HD_;
    const int tid = threadIdx.x;
    const int ty = tid >> 4, tx = tid & 15;
    float acc[4][4] = {};
    #pragma unroll
    for (int k0 = 0; k0 < HD_; k0 += 16) {
        #pragma unroll
        for (int i = 0; i < 4; i++) {
            int idx = tid + i * 256;
            int r = idx >> 4, kk = idx & 15;
            int gq = q0 + r;
            As[r][kk] = (gq < Q_)
                ? qbase[(size_t)gq * (B_ * D_) + k0 + kk] + pbu[h * HD_ + k0 + kk]
                : 0.f;
            int gk = c0 + r;
            Bs[r][kk] = (gk < KV_)
                ? kbase[(size_t)gk * (B_ * 2 * D_) + k0 + kk]
                : 0.f;
        }
        __syncthreads();
        #pragma unroll
        for (int kk = 0; kk < 16; kk++) {
            float av[4], bv[4];
            #pragma unroll
            for (int a = 0; a < 4; a++) av[a] = As[ty * 4 + a][kk];
            #pragma unroll
            for (int b2 = 0; b2 < 4; b2++) bv[b2] = Bs[tx * 4 + b2][kk];
            #pragma unroll
            for (int a = 0; a < 4; a++)
                #pragma unroll
                for (int b2 = 0; b2 < 4; b2++)
                    acc[a][b2] += av[a] * bv[b2];
        }
        __syncthreads();
    }
    float* crow = g_scores + (size_t)bh * Q_ * KV_;
    #pragma unroll
    for (int a = 0; a < 4; a++) {
        int gq = q0 + ty * 4 + a;
        if (gq >= Q_) continue;
        #pragma unroll
        for (int b2 = 0; b2 < 4; b2++) {
            int gk = c0 + tx * 4 + b2;
            if (gk >= KV_) continue;
            crow[(size_t)gq * KV_ + gk] = acc[a][b2];
        }
    }
}

// ---------------- matrix_bd (banded): scores[bh][R+u][M+R+j] += qv[u]·pos[U-1-u+j] ----------------
__global__ void attn_bd_kernel(const float* __restrict__ pbv)
{
    const int bh = blockIdx.z, b = bh >> 3, h = bh & 7;
    const int u0 = blockIdx.y * 64, j0 = blockIdx.x * 64;
    __shared__ float qv_s[64][64];     // [u][k]
    __shared__ float pos_s[64][127];   // [k][p_local], ld=127 (odd -> conflict-free)
    const int tid = threadIdx.x;

    // load qv tile (+pos_bias_v)
    #pragma unroll
    for (int i = 0; i < 16; i++) {
        int idx = tid + i * 256;
        int r = idx >> 6, k = idx & 63;
        qv_s[r][k] = g_q[((size_t)(R_ + u0 + r) * B_ + b) * D_ + h * HD_ + k]
                   + pbv[h * HD_ + k];
    }
    // load pos span [p_min, p_min+126], transposed
    const int p_min = U_ - 64 - u0 + j0;   // always in [0, PE-127]
    #pragma unroll
    for (int i = 0; i < 32; i++) {
        int idx = tid + i * 256;
        if (idx < 127 * 64) {
            int p = idx >> 6, k = idx & 63;
            pos_s[k][p] = g_pos[(size_t)(p_min + p) * D_ + h * HD_ + k];
        }
    }
    __syncthreads();

    const int ty = tid >> 4, tx = tid & 15;
    const int uu0 = ty * 4, jj0 = tx * 4;
    const int base = 63 - uu0 + jj0 - 3;   // in [0,120]
    float acc[4][4] = {};
    #pragma unroll 4
    for (int kk = 0; kk < 64; kk++) {
        float av[4];
        #pragma unroll
        for (int a = 0; a < 4; a++) av[a] = qv_s[uu0 + a][kk];
        float pv[7];
        #pragma unroll
        for (int i = 0; i < 7; i++) pv[i] = pos_s[kk][base + i];
        #pragma unroll
        for (int a = 0; a < 4; a++)
            #pragma unroll
            for (int b2 = 0; b2 < 4; b2++)
                acc[a][b2] += av[a] * pv[3 - a + b2];  // p_local = 63-(uu0+a)+(jj0+b2)
    }
    float* crow = g_scores + (size_t)bh * Q_ * KV_;
    #pragma unroll
    for (int a = 0; a < 4; a++) {
        int gq = R_ + u0 + uu0 + a;
        #pragma unroll
        for (int b2 = 0; b2 < 4; b2++) {
            int gk = M_ + R_ + j0 + jj0 + b2;
            crow[(size_t)gq * KV_ + gk] += acc[a][b2];
        }
    }
}

// ---------------- fused scale + mask + softmax (in-place on g_scores) ----------------
__global__ void softmax_kernel(const int* __restrict__ lengths)
{
    const int q = blockIdx.x;
    const int bh = blockIdx.y;
    const int b = bh >> 3;
    float* row = g_scores + ((size_t)bh * Q_ + q) * KV_;

    // chunk id of this query row
    const int c = (q < R_) ? (q / RC_) : (q < R_ + U_ ? (q - R_) / CL_ : (q - R_ - U_));
    const int limit = KV_ - U_ + lengths[b];
    const int a1 = M_ + c * RC_, a2 = a1 + RC_;
    const int a3 = M_ + R_ + (c > 0 ? c - 1 : 0) * CL_, a4 = M_ + R_ + (c + 1) * CL_;

    const int t = threadIdx.x;  // 128 threads
    float vals[9];
    float mx = -3.4e38f;
    #pragma unroll
    for (int i = 0; i < 9; i++) {
        int col = t + i * 128;
        float v = NEG_INF_;
        if (col < KV_) {
            bool ok = (col < c) || (col >= a1 && col < a2) || (col >= a3 && col < a4);
            if (ok && col < limit) v = row[col] * SCALING_;
        }
        vals[i] = v;
        mx = fmaxf(mx, v);
    }
    __shared__ float red[4];
    #pragma unroll
    for (int o = 16; o > 0; o >>= 1) mx = fmaxf(mx, __shfl_xor_sync(~0u, mx, o));
    if ((t & 31) == 0) red[t >> 5] = mx;
    __syncthreads();
    mx = fmaxf(fmaxf(red[0], red[1]), fmaxf(red[2], red[3]));
    __syncthreads();

    float s = 0.f;
    #pragma unroll
    for (int i = 0; i < 9; i++) {
        float e = __expf(vals[i] - mx);   // masked -> exp(~-1e8) == 0
        vals[i] = e;
        s += e;
    }
    #pragma unroll
    for (int o = 16; o > 0; o >>= 1) s += __shfl_xor_sync(~0u, s, o);
    if ((t & 31) == 0) red[t >> 5] = s;
    __syncthreads();
    s = red[0] + red[1] + red[2] + red[3];
    const float inv = 1.f / s;
    #pragma unroll
    for (int i = 0; i < 9; i++) {
        int col = t + i * 128;
        if (col < KV_) row[col] = vals[i] * inv;
    }
}

// ---------------- attn = probs @ v ----------------
__global__ void attn_pv_kernel()
{
    const int bh = blockIdx.y, b = bh >> 3, h = bh & 7;
    const int q0 = blockIdx.x * 64;
    __shared__ float Ps[64][65];  // [q][k]
    __shared__ float Vs[64][65];  // [k][d]
    const float* prow = g_scores + (size_t)bh * Q_ * KV_;
    const float* vbase = g_kv + (size_t)b * 2 * D_ + D_ + h * HD_;
    const int tid = threadIdx.x;
    const int ty = tid >> 4, tx = tid & 15;
    float acc[4][4] = {};
    for (int k0 = 0; k0 < KV_; k0 += 64) {
        #pragma unroll
        for (int i = 0; i < 16; i++) {
            int idx = tid + i * 256;
            int r = idx >> 6, cc = idx & 63;
            int gq = q0 + r, gk = k0 + cc;
            Ps[r][cc] = (gq < Q_ && gk < KV_) ? prow[(size_t)gq * KV_ + gk] : 0.f;
            int vk = k0 + r;
            Vs[r][cc] = (vk < KV_) ? vbase[(size_t)vk * (B_ * 2 * D_) + cc] : 0.f;
        }
        __syncthreads();
        #pragma unroll 8
        for (int kk = 0; kk < 64; kk++) {
            float av[4], bv[4];
            #pragma unroll
            for (int a = 0; a < 4; a++) av[a] = Ps[ty * 4 + a][kk];
            #pragma unroll
            for (int b2 = 0; b2 < 4; b2++) bv[b2] = Vs[kk][tx * 4 + b2];
            #pragma unroll
            for (int a = 0; a < 4; a++)
                #pragma unroll
                for (int b2 = 0; b2 < 4; b2++)
                    acc[a][b2] += av[a] * bv[b2];
        }
        __syncthreads();
    }
    #pragma unroll
    for (int a = 0; a < 4; a++) {
        int gq = q0 + ty * 4 + a;
        if (gq >= Q_) continue;
        #pragma unroll
        for (int b2 = 0; b2 < 4; b2++) {
            g_attn[((size_t)gq * B_ + b) * D_ + h * HD_ + tx * 4 + b2] = acc[a][b2];
        }
    }
}

// ---------------- out_mem = clip(attn[R+U:], -10, 10) ----------------
__global__ void clip_kernel(float* __restrict__ out)
{
    const size_t off = (size_t)(R_ + U_) * B_ * D_;
    int i = blockIdx.x * 256 + threadIdx.x;  // 65536 elems total
    float v = g_attn[off + i];
    out[off + i] = fminf(10.f, fmaxf(-10.f, v));
}

// ---------------- launch ----------------
extern "C" void kernel_launch(void* const* d_in, const int* in_sizes, int n_in,
                              void* d_out, int out_size)
{
    const float* utt    = (const float*)d_in[0];
    const int*   lens   = (const int*)  d_in[1];
    const float* rc     = (const float*)d_in[2];
    const float* summ   = (const float*)d_in[3];
    const float* mem    = (const float*)d_in[4];
    // d_in[5] = attention_mask (recomputed analytically, unused)
    const float* pos_e  = (const float*)d_in[6];
    const float* W_kv   = (const float*)d_in[7];
    const float* b_kv   = (const float*)d_in[8];
    const float* W_q    = (const float*)d_in[9];
    const float* b_q    = (const float*)d_in[10];
    const float* W_out  = (const float*)d_in[11];
    const float* b_out  = (const float*)d_in[12];
    const float* W_pos  = (const float*)d_in[13];
    const float* pbu    = (const float*)d_in[14];
    const float* pbv    = (const float*)d_in[15];
    float* out = (float*)d_out;

    float *q_buf, *kv_buf, *pos_buf;
    cudaGetSymbolAddress((void**)&q_buf,   g_q);
    cudaGetSymbolAddress((void**)&kv_buf,  g_kv);
    cudaGetSymbolAddress((void**)&pos_buf, g_pos);
    float* attn_buf;
    cudaGetSymbolAddress((void**)&attn_buf, g_attn);

    const dim3 blk(256);

    // ---- query projection (3 concat segments) ----
    gemm_nt_kernel<<<dim3(8,   8), blk>>>(rc,   D_, W_q, D_, q_buf,                      D_, R_ * B_, D_, D_, b_q);
    gemm_nt_kernel<<<dim3(8, 128), blk>>>(utt,  D_, W_q, D_, q_buf + (size_t)R_*B_*D_,   D_, U_ * B_, D_, D_, b_q);
    gemm_nt_kernel<<<dim3(8,   2), blk>>>(summ, D_, W_q, D_, q_buf + (size_t)(R_+U_)*B_*D_, D_, S_ * B_, D_, D_, b_q);

    // ---- kv projection (3 concat segments) ----
    gemm_nt_kernel<<<dim3(16,   2), blk>>>(mem, D_, W_kv, D_, kv_buf,                          2*D_, M_ * B_, 2*D_, D_, b_kv);
    gemm_nt_kernel<<<dim3(16,   8), blk>>>(rc,  D_, W_kv, D_, kv_buf + (size_t)M_*B_*2*D_,     2*D_, R_ * B_, 2*D_, D_, b_kv);
    gemm_nt_kernel<<<dim3(16, 128), blk>>>(utt, D_, W_kv, D_, kv_buf + (size_t)(M_+R_)*B_*2*D_,2*D_, U_ * B_, 2*D_, D_, b_kv);

    // ---- positional projection ----
    gemm_nt_kernel<<<dim3(8, 32), blk>>>(pos_e, D_, W_pos, D_, pos_buf, D_, PE_, D_, D_, nullptr);

    // ---- matrix_ac ----
    attn_ac_kernel<<<dim3(18, 18, 64), blk>>>(pbu);

    // ---- matrix_bd (banded, accumulates into scores) ----
    attn_bd_kernel<<<dim3(16, 16, 64), blk>>>(pbv);

    // ---- scale + mask + softmax ----
    softmax_kernel<<<dim3(Q_, 64), dim3(128)>>>(lens);

    // ---- attn = P @ V ----
    attn_pv_kernel<<<dim3(18, 64), blk>>>();

    // ---- output projection + clipped memory output ----
    gemm_nt_kernel<<<dim3(8, 136), blk>>>(attn_buf, D_, W_out, D_, out, D_, (R_ + U_) * B_, D_, D_, b_out);
    clip_kernel<<<dim3(256), blk>>>(out);
}

// round 2
// speedup vs baseline: 1.9646x; 1.9646x over previous
#include <cuda_runtime.h>
#include <cuda_bf16.h>
#include <cstddef>

// ---------------- problem constants ----------------
#define U_  1024
#define B_  8
#define D_  512
#define H_  8
#define HD_ 64
#define CL_ 64
#define RC_ 4
#define C_  16
#define R_  64          // C_*RC_
#define S_  16          // C_
#define M_  15          // C_-1
#define Q_  1104        // R_+U_+S_
#define KV_ 1103        // M_+R_+U_
#define NEG_INF_ (-100000000.0f)
#define SCALING_ 0.125f // HD^-0.5

// ---------------- scratch (device globals; no allocs) ----------------
__device__ float g_q[(size_t)Q_ * B_ * D_];        // [qpos*B+b][d]
__device__ float g_kv[(size_t)KV_ * B_ * 2 * D_];  // [kvpos*B+b][2d]
__device__ float g_pos[(size_t)191 * D_];          // pos rows p = U-128 .. U+62
__device__ float g_attn[(size_t)Q_ * B_ * D_];     // [qpos*B+b][d]

// =====================================================================
// Projection GEMM: C[r][n] = sum_k A(r)[k] * W[n][k] + bias[n]
// A is a concat of up to 3 row-segments (A0 rows [0,r1), A1 [r1,r2), A2 rest).
// Tile 128x64, K-panel 16, 256 threads, 8x4 per thread, transposed smem tiles.
// =====================================================================
__global__ __launch_bounds__(256) void gemm_cat3(
    const float* __restrict__ A0, const float* __restrict__ A1,
    const float* __restrict__ A2, int r1, int r2,
    const float* __restrict__ W, float* __restrict__ Cm,
    int Mr, int Nc, int ldc, const float* __restrict__ bias)
{
    __shared__ float At[16][132];
    __shared__ float Bt[16][68];
    const int row0 = blockIdx.y * 128, col0 = blockIdx.x * 64;
    const int tid = threadIdx.x;
    const int ty = tid >> 4, tx = tid & 15;
    float acc[8][4] = {};

    for (int k0 = 0; k0 < D_; k0 += 16) {
        #pragma unroll
        for (int i = 0; i < 8; i++) {
            int idx = tid + i * 256;
            int m = idx >> 4, kk = idx & 15;
            int gr = row0 + m;
            float v = 0.f;
            if (gr < Mr) {
                const float* src; int lr;
                if (gr < r1)      { src = A0; lr = gr; }
                else if (gr < r2) { src = A1; lr = gr - r1; }
                else              { src = A2; lr = gr - r2; }
                v = src[(size_t)lr * D_ + k0 + kk];
            }
            At[kk][m] = v;
        }
        #pragma unroll
        for (int i = 0; i < 4; i++) {
            int idx = tid + i * 256;
            int n = idx >> 4, kk = idx & 15;
            int gc = col0 + n;
            Bt[kk][n] = (gc < Nc) ? W[(size_t)gc * D_ + k0 + kk] : 0.f;
        }
        __syncthreads();
        #pragma unroll
        for (int kk = 0; kk < 16; kk++) {
            float4 a0 = *(const float4*)&At[kk][ty * 8];
            float4 a1 = *(const float4*)&At[kk][ty * 8 + 4];
            float4 b0 = *(const float4*)&Bt[kk][tx * 4];
            float av[8] = {a0.x, a0.y, a0.z, a0.w, a1.x, a1.y, a1.z, a1.w};
            float bv[4] = {b0.x, b0.y, b0.z, b0.w};
            #pragma unroll
            for (int a = 0; a < 8; a++)
                #pragma unroll
                for (int j = 0; j < 4; j++)
                    acc[a][j] += av[a] * bv[j];
        }
        __syncthreads();
    }
    #pragma unroll
    for (int a = 0; a < 8; a++) {
        int gr = row0 + ty * 8 + a;
        if (gr >= Mr) continue;
        #pragma unroll
        for (int j = 0; j < 4; j++) {
            int gc = col0 + tx * 4 + j;
            if (gc >= Nc) continue;
            float v = acc[a][j];
            if (bias) v += bias[gc];
            Cm[(size_t)gr * ldc + gc] = v;
        }
    }
}

// =====================================================================
// Fused compact attention: one CTA per (chunk c, batch-head bh).
// Rows: 4 rc + 64 utt + 1 summary = 69. Cols: c mem + 4 rc + n_utt (<=147).
// AC + banded BD + mask + softmax + PV, all in shared memory.
// =====================================================================
__global__ __launch_bounds__(256) void fused_attn_kernel(
    const int* __restrict__ lengths,
    const float* __restrict__ pbu,
    const float* __restrict__ pbv)
{
    extern __shared__ float smf[];
    float* Qs      = smf;               // 80 x 66
    float* Kt      = Qs + 80 * 66;      // 64 x 161 (K transposed; later V)
    float* Pt      = Kt + 64 * 161;     // 64 x 193 (pos transposed)
    float* Ss      = Pt + 64 * 193;     // 80 x 161 (scores)
    float* bias_u  = Ss + 80 * 161;     // 160
    float* bias_vp = bias_u + 160;      // 192
    float* pbu_s   = bias_vp + 192;     // 64
    float* pbv_s   = pbu_s + 64;        // 64

    const int c = blockIdx.x, bh = blockIdx.y;
    const int b = bh >> 3, h = bh & 7;
    const int tid = threadIdx.x;
    const int ustart = (c == 0) ? 0 : (c - 1) * CL_;
    const int n_utt = (c == 0) ? 64 : 128;
    const int ncols = c + 4 + n_utt;
    const int len_b = lengths[b];

    // ---- load Q rows (80 rows, zero-padded past 69) ----
    for (int idx = tid; idx < 80 * 64; idx += 256) {
        int r = idx >> 6, k = idx & 63;
        float v = 0.f;
        if (r < 69) {
            int qrow = (r < 4) ? c * 4 + r
                     : (r < 68 ? R_ + c * 64 + (r - 4) : R_ + U_ + c);
            v = g_q[((size_t)qrow * B_ + b) * D_ + h * 64 + k];
        }
        Qs[r * 66 + k] = v;
    }
    // ---- load K cols (transposed), zero-padded ----
    for (int idx = tid; idx < 160 * 64; idx += 256) {
        int i = idx >> 6, k = idx & 63;
        float v = 0.f;
        if (i < ncols) {
            int kvrow = (i < c) ? i
                      : (i < c + 4 ? M_ + c * 4 + (i - c)
                                   : M_ + R_ + ustart + (i - c - 4));
            v = g_kv[((size_t)kvrow * B_ + b) * (2 * D_) + h * 64 + k];
        }
        Kt[k * 161 + i] = v;
    }
    // ---- load pos (transposed) ----
    for (int idx = tid; idx < 191 * 64; idx += 256) {
        int pl = idx >> 6, k = idx & 63;
        Pt[k * 193 + pl] = g_pos[(size_t)pl * D_ + h * 64 + k];
    }
    if (tid < 64) pbu_s[tid] = pbu[h * 64 + tid];
    else if (tid < 128) pbv_s[tid - 64] = pbv[h * 64 + tid - 64];
    __syncthreads();

    // ---- bias_u[i] = pbu . K_i ; bias_vp[pl] = pbv . pos_pl ----
    if (tid < 160) {
        float s = 0.f;
        if (tid < ncols) {
            #pragma unroll 8
            for (int k = 0; k < 64; k++) s += pbu_s[k] * Kt[k * 161 + tid];
        }
        bias_u[tid] = s;
    }
    for (int pl = tid; pl < 191; pl += 256) {
        float s = 0.f;
        #pragma unroll 8
        for (int k = 0; k < 64; k++) s += pbv_s[k] * Pt[k * 193 + pl];
        bias_vp[pl] = s;
    }
    __syncthreads();

    const int ty = tid >> 4, tx = tid & 15;

    // ---- phase C1: AC scores (q . k), 5x10 per thread ----
    {
        float acc[5][10] = {};
        for (int kk = 0; kk < 64; kk++) {
            float av[5], bv[10];
            #pragma unroll
            for (int a = 0; a < 5; a++) av[a] = Qs[(ty + 16 * a) * 66 + kk];
            #pragma unroll
            for (int j = 0; j < 10; j++) bv[j] = Kt[kk * 161 + tx + 16 * j];
            #pragma unroll
            for (int a = 0; a < 5; a++)
                #pragma unroll
                for (int j = 0; j < 10; j++)
                    acc[a][j] += av[a] * bv[j];
        }
        #pragma unroll
        for (int a = 0; a < 5; a++)
            #pragma unroll
            for (int j = 0; j < 10; j++)
                Ss[(ty + 16 * a) * 161 + tx + 16 * j] = acc[a][j] + bias_u[tx + 16 * j];
    }
    __syncthreads();

    // ---- phase C2: banded BD (utterance rows x utterance cols) ----
    {
        const int pbase = (c == 0) ? 127 : 63;
        const int plb = pbase - ty + tx;   // pl = plb + 16*(bb-a)
        float accb[4][8] = {};
        for (int kk = 0; kk < 64; kk++) {
            float qv[4];
            #pragma unroll
            for (int a = 0; a < 4; a++) qv[a] = Qs[(4 + ty + 16 * a) * 66 + kk];
            float pv[11];
            #pragma unroll
            for (int t = 0; t < 11; t++) {
                int pl = plb + 16 * (t - 3);
                pl = (pl < 0) ? 0 : (pl > 190 ? 190 : pl);  // clamped only for invalid cells
                pv[t] = Pt[kk * 193 + pl];
            }
            #pragma unroll
            for (int a = 0; a < 4; a++)
                #pragma unroll
                for (int bb = 0; bb < 8; bb++)
                    accb[a][bb] += qv[a] * pv[bb - a + 3];
        }
        #pragma unroll
        for (int a = 0; a < 4; a++) {
            int u = ty + 16 * a;
            #pragma unroll
            for (int bb = 0; bb < 8; bb++) {
                int j = tx + 16 * bb;
                if (j < n_utt) {
                    int pl = plb + 16 * (bb - a);
                    Ss[(4 + u) * 161 + (c + 4 + j)] += accb[a][bb] + bias_vp[pl];
                }
            }
        }
    }
    __syncthreads();

    // ---- load V into Kt (overlap with softmax) ----
    for (int idx = tid; idx < ncols * 64; idx += 256) {
        int i = idx >> 6, k = idx & 63;
        int kvrow = (i < c) ? i
                  : (i < c + 4 ? M_ + c * 4 + (i - c)
                               : M_ + R_ + ustart + (i - c - 4));
        Kt[k * 161 + i] = g_kv[((size_t)kvrow * B_ + b) * (2 * D_) + D_ + h * 64 + k];
    }

    // ---- softmax (scale + length mask), one warp per row ----
    {
        const int warp = tid >> 5, lane = tid & 31;
        const int limit_j = len_b - ustart;
        const int uc0 = c + 4;
        for (int r = warp; r < 69; r += 8) {
            float vals[5];
            float mx = -3.4e38f;
            #pragma unroll
            for (int g = 0; g < 5; g++) {
                int i = lane + 32 * g;
                float v = -3.4e38f;
                if (i < ncols) {
                    v = Ss[r * 161 + i] * SCALING_;
                    if (i >= uc0 && (i - uc0) >= limit_j) v = NEG_INF_;
                }
                vals[g] = v;
                mx = fmaxf(mx, v);
            }
            #pragma unroll
            for (int o = 16; o > 0; o >>= 1) mx = fmaxf(mx, __shfl_xor_sync(~0u, mx, o));
            float sum = 0.f;
            #pragma unroll
            for (int g = 0; g < 5; g++) {
                float e = __expf(vals[g] - mx);
                vals[g] = e;
                sum += e;
            }
            #pragma unroll
            for (int o = 16; o > 0; o >>= 1) sum += __shfl_xor_sync(~0u, sum, o);
            float inv = 1.f / sum;
            #pragma unroll
            for (int g = 0; g < 5; g++) {
                int i = lane + 32 * g;
                if (i < ncols) Ss[r * 161 + i] = vals[g] * inv;
            }
        }
    }
    __syncthreads();

    // ---- PV: out[r][d] = sum_i P[r][i] * V[i][d] ----
    {
        float acco[5][4] = {};
        for (int i = 0; i < ncols; i++) {
            float sv[5];
            #pragma unroll
            for (int a = 0; a < 5; a++) sv[a] = Ss[(ty + 16 * a) * 161 + i];
            float vv[4];
            #pragma unroll
            for (int dd = 0; dd < 4; dd++) vv[dd] = Kt[(tx + 16 * dd) * 161 + i];
            #pragma unroll
            for (int a = 0; a < 5; a++)
                #pragma unroll
                for (int dd = 0; dd < 4; dd++)
                    acco[a][dd] += sv[a] * vv[dd];
        }
        #pragma unroll
        for (int a = 0; a < 5; a++) {
            int r = ty + 16 * a;
            if (r < 69) {
                int qrow = (r < 4) ? c * 4 + r
                         : (r < 68 ? R_ + c * 64 + (r - 4) : R_ + U_ + c);
                float* dst = g_attn + ((size_t)qrow * B_ + b) * D_ + h * 64 + tx;
                #pragma unroll
                for (int dd = 0; dd < 4; dd++) dst[16 * dd] = acco[a][dd];
            }
        }
    }
}

// ---------------- out_mem = clip(attn[R+U:], -10, 10) ----------------
__global__ void clip_kernel(float* __restrict__ out)
{
    const size_t off = (size_t)(R_ + U_) * B_ * D_;
    int i = blockIdx.x * 256 + threadIdx.x;  // 65536 elems
    float v = g_attn[off + i];
    out[off + i] = fminf(10.f, fmaxf(-10.f, v));
}

// ---------------- launch ----------------
extern "C" void kernel_launch(void* const* d_in, const int* in_sizes, int n_in,
                              void* d_out, int out_size)
{
    const float* utt    = (const float*)d_in[0];
    const int*   lens   = (const int*)  d_in[1];
    const float* rc     = (const float*)d_in[2];
    const float* summ   = (const float*)d_in[3];
    const float* mem    = (const float*)d_in[4];
    // d_in[5] = attention_mask (recomputed analytically, unused)
    const float* pos_e  = (const float*)d_in[6];
    const float* W_kv   = (const float*)d_in[7];
    const float* b_kv   = (const float*)d_in[8];
    const float* W_q    = (const float*)d_in[9];
    const float* b_q    = (const float*)d_in[10];
    const float* W_out  = (const float*)d_in[11];
    const float* b_out  = (const float*)d_in[12];
    const float* W_pos  = (const float*)d_in[13];
    const float* pbu    = (const float*)d_in[14];
    const float* pbv    = (const float*)d_in[15];
    float* out = (float*)d_out;

    float *q_buf, *kv_buf, *pos_buf, *attn_buf;
    cudaGetSymbolAddress((void**)&q_buf,    g_q);
    cudaGetSymbolAddress((void**)&kv_buf,   g_kv);
    cudaGetSymbolAddress((void**)&pos_buf,  g_pos);
    cudaGetSymbolAddress((void**)&attn_buf, g_attn);

    const size_t SMEM_ATTN = (size_t)(80*66 + 64*161 + 64*193 + 80*161 + 160 + 192 + 64 + 64) * 4;
    cudaFuncSetAttribute(fused_attn_kernel,
                         cudaFuncAttributeMaxDynamicSharedMemorySize, (int)SMEM_ATTN);

    const dim3 blk(256);

    // query projection: concat [rc(512 rows), utt(8192), summ(128)] -> g_q
    gemm_cat3<<<dim3(8, 69), blk>>>(rc, utt, summ, 512, 512 + 8192,
                                    W_q, q_buf, Q_ * B_, D_, D_, b_q);
    // kv projection: concat [mem(120), rc(512), utt(8192)] -> g_kv
    gemm_cat3<<<dim3(16, 69), blk>>>(mem, rc, utt, 120, 120 + 512,
                                     W_kv, kv_buf, KV_ * B_, 2 * D_, 2 * D_, b_kv);
    // pos projection: only rows p = U-128 .. U+62 (191 rows)
    const float* pos_src = pos_e + (size_t)(U_ - 128) * D_;
    gemm_cat3<<<dim3(8, 2), blk>>>(pos_src, pos_src, pos_src, 191, 191,
                                   W_pos, pos_buf, 191, D_, D_, nullptr);

    // fused compact attention
    fused_attn_kernel<<<dim3(C_, 64), blk, SMEM_ATTN>>>(lens, pbu, pbv);

    // output projection (rc+utt rows) + clipped memory output
    gemm_cat3<<<dim3(8, 68), blk>>>(attn_buf, attn_buf, attn_buf,
                                    (R_ + U_) * B_, (R_ + U_) * B_,
                                    W_out, out, (R_ + U_) * B_, D_, D_, b_out);
    clip_kernel<<<dim3(256), blk>>>(out);
}

// round 3
// speedup vs baseline: 2.1950x; 1.1173x over previous
#include <cuda_runtime.h>
#include <cuda_bf16.h>
#include <cstddef>

// ---------------- problem constants ----------------
#define U_  1024
#define B_  8
#define D_  512
#define H_  8
#define HD_ 64
#define CL_ 64
#define RC_ 4
#define C_  16
#define R_  64
#define S_  16
#define M_  15
#define Q_  1104
#define KV_ 1103
#define NEG_INF_ (-100000000.0f)
#define SCALING_ 0.125f

// ---------------- packed f32x2 helpers (sm_103a FFMA2) ----------------
typedef unsigned long long u64t;
__device__ __forceinline__ u64t pk2(float v) {
    u64t r; asm("mov.b64 %0, {%1, %1};" : "=l"(r) : "f"(v)); return r;
}
__device__ __forceinline__ void fma2(u64t& d, u64t a, u64t b) {
    asm("fma.rn.f32x2 %0, %1, %2, %0;" : "+l"(d) : "l"(a), "l"(b));
}
__device__ __forceinline__ u64t add2(u64t a, u64t b) {
    u64t r; asm("add.rn.f32x2 %0, %1, %2;" : "=l"(r) : "l"(a), "l"(b)); return r;
}
__device__ __forceinline__ float2 upk(u64t v) {
    float2 f; asm("mov.b64 {%0, %1}, %2;" : "=f"(f.x), "=f"(f.y) : "l"(v)); return f;
}

// ---------------- scratch (device globals; no allocs) ----------------
__device__ float g_q[(size_t)Q_ * B_ * D_];
__device__ float g_kv[(size_t)KV_ * B_ * 2 * D_];
__device__ float g_pos[(size_t)191 * D_];          // pos rows p = U-128 .. U+62
__device__ float g_attn[(size_t)Q_ * B_ * D_];

// =====================================================================
// Projection GEMM (concat of <=3 row segments), 128x64 tile, 256 thr,
// 8x4 per thread, FFMA2 pairs along the row dimension.
// =====================================================================
__global__ __launch_bounds__(256) void gemm_cat3(
    const float* __restrict__ A0, const float* __restrict__ A1,
    const float* __restrict__ A2, int r1, int r2,
    const float* __restrict__ W, float* __restrict__ Cm,
    int Mr, int Nc, int ldc, const float* __restrict__ bias)
{
    __shared__ float At[16][132];
    __shared__ float Bt[16][68];
    const int row0 = blockIdx.y * 128, col0 = blockIdx.x * 64;
    const int tid = threadIdx.x;
    const int ty = tid >> 4, tx = tid & 15;
    u64t acc2[4][4] = {};   // [row-pair][col] : rows ty*8+2ap{,+1}, col tx*4+j

    for (int k0 = 0; k0 < D_; k0 += 16) {
        #pragma unroll
        for (int i = 0; i < 8; i++) {
            int idx = tid + i * 256;
            int m = idx >> 4, kk = idx & 15;
            int gr = row0 + m;
            float v = 0.f;
            if (gr < Mr) {
                const float* src; int lr;
                if (gr < r1)      { src = A0; lr = gr; }
                else if (gr < r2) { src = A1; lr = gr - r1; }
                else              { src = A2; lr = gr - r2; }
                v = src[(size_t)lr * D_ + k0 + kk];
            }
            At[kk][m] = v;
        }
        #pragma unroll
        for (int i = 0; i < 4; i++) {
            int idx = tid + i * 256;
            int n = idx >> 4, kk = idx & 15;
            int gc = col0 + n;
            Bt[kk][n] = (gc < Nc) ? W[(size_t)gc * D_ + k0 + kk] : 0.f;
        }
        __syncthreads();
        #pragma unroll
        for (int kk = 0; kk < 16; kk++) {
            const u64t* ap = reinterpret_cast<const u64t*>(&At[kk][ty * 8]);
            u64t av0 = ap[0], av1 = ap[1], av2 = ap[2], av3 = ap[3];
            float4 b4 = *(const float4*)&Bt[kk][tx * 4];
            u64t bb0 = pk2(b4.x), bb1 = pk2(b4.y), bb2 = pk2(b4.z), bb3 = pk2(b4.w);
            fma2(acc2[0][0], av0, bb0); fma2(acc2[0][1], av0, bb1);
            fma2(acc2[0][2], av0, bb2); fma2(acc2[0][3], av0, bb3);
            fma2(acc2[1][0], av1, bb0); fma2(acc2[1][1], av1, bb1);
            fma2(acc2[1][2], av1, bb2); fma2(acc2[1][3], av1, bb3);
            fma2(acc2[2][0], av2, bb0); fma2(acc2[2][1], av2, bb1);
            fma2(acc2[2][2], av2, bb2); fma2(acc2[2][3], av2, bb3);
            fma2(acc2[3][0], av3, bb0); fma2(acc2[3][1], av3, bb1);
            fma2(acc2[3][2], av3, bb2); fma2(acc2[3][3], av3, bb3);
        }
        __syncthreads();
    }
    #pragma unroll
    for (int ap = 0; ap < 4; ap++) {
        int gr0 = row0 + ty * 8 + 2 * ap;
        #pragma unroll
        for (int j = 0; j < 4; j++) {
            int gc = col0 + tx * 4 + j;
            if (gc >= Nc) continue;
            float2 v = upk(acc2[ap][j]);
            float bv = bias ? bias[gc] : 0.f;
            if (gr0 < Mr)     Cm[(size_t)gr0 * ldc + gc]       = v.x + bv;
            if (gr0 + 1 < Mr) Cm[(size_t)(gr0 + 1) * ldc + gc] = v.y + bv;
        }
    }
}

// =====================================================================
// Fused compact attention: one CTA per (chunk c, bh). 512 threads.
// =====================================================================
__global__ __launch_bounds__(512) void fused_attn_kernel(
    const int* __restrict__ lengths,
    const float* __restrict__ pbu,
    const float* __restrict__ pbv)
{
    extern __shared__ float smf[];
    float* Qs      = smf;                 // 96 x 66 (rows >=69 zero)
    float* Kt      = Qs + 96 * 66;        // 64 x 162 [k][i]
    float* Pt      = Kt + 64 * 162;       // 64 x 193 [k][pl]
    float* Ss      = Pt + 64 * 193;       // 80 x 162 scores [r][i]
    float* Vt      = Ss + 80 * 162;       // 160 x 66 [i][d]
    float* bias_u  = Vt + 160 * 66;       // 160
    float* bias_vp = bias_u + 160;        // 192
    float* pbu_s   = bias_vp + 192;       // 64
    float* pbv_s   = pbu_s + 64;          // 64

    const int c = blockIdx.x, bh = blockIdx.y;
    const int b = bh >> 3, h = bh & 7;
    const int tid = threadIdx.x;
    const int ustart = (c == 0) ? 0 : (c - 1) * CL_;
    const int n_utt = (c == 0) ? 64 : 128;
    const int ncols = c + 4 + n_utt;
    const int len_b = lengths[b];

    // ---- loads ----
    for (int idx = tid; idx < 96 * 64; idx += 512) {
        int r = idx >> 6, k = idx & 63;
        float v = 0.f;
        if (r < 69) {
            int qrow = (r < 4) ? c * 4 + r
                     : (r < 68 ? R_ + c * 64 + (r - 4) : R_ + U_ + c);
            v = g_q[((size_t)qrow * B_ + b) * D_ + h * 64 + k];
        }
        Qs[r * 66 + k] = v;
    }
    for (int idx = tid; idx < 160 * 64; idx += 512) {
        int i = idx >> 6, k = idx & 63;
        float v = 0.f;
        if (i < ncols) {
            int kvrow = (i < c) ? i
                      : (i < c + 4 ? M_ + c * 4 + (i - c)
                                   : M_ + R_ + ustart + (i - c - 4));
            v = g_kv[((size_t)kvrow * B_ + b) * (2 * D_) + h * 64 + k];
        }
        Kt[k * 162 + i] = v;
    }
    for (int idx = tid; idx < 191 * 64; idx += 512) {
        int pl = idx >> 6, k = idx & 63;
        Pt[k * 193 + pl] = g_pos[(size_t)pl * D_ + h * 64 + k];
    }
    for (int idx = tid; idx < ncols * 64; idx += 512) {
        int i = idx >> 6, k = idx & 63;
        int kvrow = (i < c) ? i
                  : (i < c + 4 ? M_ + c * 4 + (i - c)
                               : M_ + R_ + ustart + (i - c - 4));
        Vt[i * 66 + k] = g_kv[((size_t)kvrow * B_ + b) * (2 * D_) + D_ + h * 64 + k];
    }
    if (tid < 64) pbu_s[tid] = pbu[h * 64 + tid];
    else if (tid < 128) pbv_s[tid - 64] = pbv[h * 64 + tid - 64];
    __syncthreads();

    // ---- bias terms ----
    if (tid < 160) {
        float s = 0.f;
        if (tid < ncols) {
            #pragma unroll 8
            for (int k = 0; k < 64; k++) s += pbu_s[k] * Kt[k * 162 + tid];
        }
        bias_u[tid] = s;
    } else if (tid < 160 + 191) {
        int pl = tid - 160;
        float s = 0.f;
        #pragma unroll 8
        for (int k = 0; k < 64; k++) s += pbv_s[k] * Pt[k * 193 + pl];
        bias_vp[pl] = s;
    }
    __syncthreads();

    const int ty = tid >> 4, tx = tid & 15;   // ty in [0,32), tx in [0,16)

    // ---- C1: AC scores. rows r=ty+32a (a<3, r<80), col pairs 2tx+32j (j<5) ----
    {
        u64t acc2[3][5] = {};
        for (int kk = 0; kk < 64; kk++) {
            u64t aa[3];
            #pragma unroll
            for (int a = 0; a < 3; a++) aa[a] = pk2(Qs[(ty + 32 * a) * 66 + kk]);
            u64t bv[5];
            #pragma unroll
            for (int j = 0; j < 5; j++)
                bv[j] = *reinterpret_cast<const u64t*>(&Kt[kk * 162 + 2 * tx + 32 * j]);
            #pragma unroll
            for (int a = 0; a < 3; a++)
                #pragma unroll
                for (int j = 0; j < 5; j++)
                    fma2(acc2[a][j], aa[a], bv[j]);
        }
        #pragma unroll
        for (int a = 0; a < 3; a++) {
            int r = ty + 32 * a;
            if (r < 80) {
                #pragma unroll
                for (int j = 0; j < 5; j++) {
                    int colp = 2 * tx + 32 * j;
                    u64t s = add2(acc2[a][j], *reinterpret_cast<const u64t*>(&bias_u[colp]));
                    *reinterpret_cast<u64t*>(&Ss[r * 162 + colp]) = s;
                }
            }
        }
    }
    __syncthreads();

    // ---- C2: banded BD. rows u=ty+32a (a<2), cols j=tx+16bb (bb<8) ----
    {
        const int pbase = (c == 0) ? 127 : 63;
        const int plb = pbase - ty + tx - 32;   // pl = plb + 16*tt, tt = bb-2a+2
        float accb[2][8] = {};
        for (int kk = 0; kk < 64; kk++) {
            float qv[2];
            #pragma unroll
            for (int a = 0; a < 2; a++) qv[a] = Qs[(4 + ty + 32 * a) * 66 + kk];
            float pv[10];
            #pragma unroll
            for (int t = 0; t < 10; t++) {
                int pl = plb + 16 * t;
                pl = (pl < 0) ? 0 : (pl > 190 ? 190 : pl);
                pv[t] = Pt[kk * 193 + pl];
            }
            #pragma unroll
            for (int a = 0; a < 2; a++)
                #pragma unroll
                for (int bb = 0; bb < 8; bb++)
                    accb[a][bb] += qv[a] * pv[bb - 2 * a + 2];
        }
        #pragma unroll
        for (int a = 0; a < 2; a++) {
            int u = ty + 32 * a;
            #pragma unroll
            for (int bb = 0; bb < 8; bb++) {
                int j = tx + 16 * bb;
                if (j < n_utt) {
                    int pl = pbase - u + j;
                    Ss[(4 + u) * 162 + (c + 4 + j)] += accb[a][bb] + bias_vp[pl];
                }
            }
        }
    }
    __syncthreads();

    // ---- softmax: one warp per row ----
    {
        const int warp = tid >> 5, lane = tid & 31;
        const int limit_j = len_b - ustart;
        const int uc0 = c + 4;
        for (int r = warp; r < 69; r += 16) {
            float vals[5];
            float mx = -3.4e38f;
            #pragma unroll
            for (int g = 0; g < 5; g++) {
                int i = lane + 32 * g;
                float v = -3.4e38f;
                if (i < ncols) {
                    v = Ss[r * 162 + i] * SCALING_;
                    if (i >= uc0 && (i - uc0) >= limit_j) v = NEG_INF_;
                }
                vals[g] = v;
                mx = fmaxf(mx, v);
            }
            #pragma unroll
            for (int o = 16; o > 0; o >>= 1) mx = fmaxf(mx, __shfl_xor_sync(~0u, mx, o));
            float sum = 0.f;
            #pragma unroll
            for (int g = 0; g < 5; g++) {
                float e = __expf(vals[g] - mx);
                vals[g] = e;
                sum += e;
            }
            #pragma unroll
            for (int o = 16; o > 0; o >>= 1) sum += __shfl_xor_sync(~0u, sum, o);
            float inv = 1.f / sum;
            #pragma unroll
            for (int g = 0; g < 5; g++) {
                int i = lane + 32 * g;
                if (i < ncols) Ss[r * 162 + i] = vals[g] * inv;
            }
        }
    }
    __syncthreads();

    // ---- PV: rows r=ty+32a (a<3), col pairs d=2tx+32dd (dd<2) ----
    {
        u64t acc2[3][2] = {};
        int rofs[3];
        #pragma unroll
        for (int a = 0; a < 3; a++) {
            int rr = ty + 32 * a; if (rr > 79) rr = 79;
            rofs[a] = rr * 162;
        }
        for (int i = 0; i < ncols; i++) {
            u64t ssv[3];
            #pragma unroll
            for (int a = 0; a < 3; a++) ssv[a] = pk2(Ss[rofs[a] + i]);
            u64t vv[2];
            #pragma unroll
            for (int dd = 0; dd < 2; dd++)
                vv[dd] = *reinterpret_cast<const u64t*>(&Vt[i * 66 + 2 * tx + 32 * dd]);
            #pragma unroll
            for (int a = 0; a < 3; a++)
                #pragma unroll
                for (int dd = 0; dd < 2; dd++)
                    fma2(acc2[a][dd], ssv[a], vv[dd]);
        }
        #pragma unroll
        for (int a = 0; a < 3; a++) {
            int r = ty + 32 * a;
            if (r < 69) {
                int qrow = (r < 4) ? c * 4 + r
                         : (r < 68 ? R_ + c * 64 + (r - 4) : R_ + U_ + c);
                float* dst = g_attn + ((size_t)qrow * B_ + b) * D_ + h * 64 + 2 * tx;
                #pragma unroll
                for (int dd = 0; dd < 2; dd++) {
                    float2 v = upk(acc2[a][dd]);
                    *reinterpret_cast<float2*>(dst + 32 * dd) = v;
                }
            }
        }
    }
}

// ---------------- out_mem = clip(attn[R+U:], -10, 10) ----------------
__global__ void clip_kernel(float* __restrict__ out)
{
    const size_t off = (size_t)(R_ + U_) * B_ * D_;
    int i = blockIdx.x * 256 + threadIdx.x;
    float v = g_attn[off + i];
    out[off + i] = fminf(10.f, fmaxf(-10.f, v));
}

// ---------------- launch ----------------
extern "C" void kernel_launch(void* const* d_in, const int* in_sizes, int n_in,
                              void* d_out, int out_size)
{
    const float* utt    = (const float*)d_in[0];
    const int*   lens   = (const int*)  d_in[1];
    const float* rc     = (const float*)d_in[2];
    const float* summ   = (const float*)d_in[3];
    const float* mem    = (const float*)d_in[4];
    const float* pos_e  = (const float*)d_in[6];
    const float* W_kv   = (const float*)d_in[7];
    const float* b_kv   = (const float*)d_in[8];
    const float* W_q    = (const float*)d_in[9];
    const float* b_q    = (const float*)d_in[10];
    const float* W_out  = (const float*)d_in[11];
    const float* b_out  = (const float*)d_in[12];
    const float* W_pos  = (const float*)d_in[13];
    const float* pbu    = (const float*)d_in[14];
    const float* pbv    = (const float*)d_in[15];
    float* out = (float*)d_out;

    float *q_buf, *kv_buf, *pos_buf, *attn_buf;
    cudaGetSymbolAddress((void**)&q_buf,    g_q);
    cudaGetSymbolAddress((void**)&kv_buf,   g_kv);
    cudaGetSymbolAddress((void**)&pos_buf,  g_pos);
    cudaGetSymbolAddress((void**)&attn_buf, g_attn);

    const size_t SMEM_ATTN =
        (size_t)(96*66 + 64*162 + 64*193 + 80*162 + 160*66 + 160 + 192 + 64 + 64) * 4;
    cudaFuncSetAttribute(fused_attn_kernel,
                         cudaFuncAttributeMaxDynamicSharedMemorySize, (int)SMEM_ATTN);

    const dim3 blk(256);

    // query projection: [rc(512), utt(8192), summ(128)] -> g_q
    gemm_cat3<<<dim3(8, 69), blk>>>(rc, utt, summ, 512, 512 + 8192,
                                    W_q, q_buf, Q_ * B_, D_, D_, b_q);
    // kv projection: [mem(120), rc(512), utt(8192)] -> g_kv
    gemm_cat3<<<dim3(16, 69), blk>>>(mem, rc, utt, 120, 120 + 512,
                                     W_kv, kv_buf, KV_ * B_, 2 * D_, 2 * D_, b_kv);
    // pos projection: rows p = U-128 .. U+62 (191)
    const float* pos_src = pos_e + (size_t)(U_ - 128) * D_;
    gemm_cat3<<<dim3(8, 2), blk>>>(pos_src, pos_src, pos_src, 191, 191,
                                   W_pos, pos_buf, 191, D_, D_, nullptr);

    // fused compact attention
    fused_attn_kernel<<<dim3(C_, 64), dim3(512), SMEM_ATTN>>>(lens, pbu, pbv);

    // output projection + clipped memory output
    gemm_cat3<<<dim3(8, 68), blk>>>(attn_buf, attn_buf, attn_buf,
                                    (R_ + U_) * B_, (R_ + U_) * B_,
                                    W_out, out, (R_ + U_) * B_, D_, D_, b_out);
    clip_kernel<<<dim3(256), blk>>>(out);
}

// round 5
// speedup vs baseline: 4.0853x; 1.8612x over previous
#include <cuda_runtime.h>
#include <cuda_bf16.h>
#include <cstddef>
#include <cstdint>

// ---------------- problem constants ----------------
#define U_  1024
#define B_  8
#define D_  512
#define H_  8
#define HD_ 64
#define CL_ 64
#define RC_ 4
#define C_  16
#define R_  64
#define S_  16
#define M_  15
#define Q_  1104
#define KV_ 1103
#define NEG_INF_ (-100000000.0f)
#define SCALING_ 0.125f

// ---------------- packed f32x2 helpers ----------------
typedef unsigned long long u64t;
__device__ __forceinline__ u64t pk2(float v) {
    u64t r; asm("mov.b64 %0, {%1, %1};" : "=l"(r) : "f"(v)); return r;
}
__device__ __forceinline__ void fma2(u64t& d, u64t a, u64t b) {
    asm("fma.rn.f32x2 %0, %1, %2, %0;" : "+l"(d) : "l"(a), "l"(b));
}
__device__ __forceinline__ u64t add2(u64t a, u64t b) {
    u64t r; asm("add.rn.f32x2 %0, %1, %2;" : "=l"(r) : "l"(a), "l"(b)); return r;
}
__device__ __forceinline__ float2 upk(u64t v) {
    float2 f; asm("mov.b64 {%0, %1}, %2;" : "=f"(f.x), "=f"(f.y) : "l"(v)); return f;
}

// ---------------- mma helpers ----------------
__device__ __forceinline__ uint32_t smem_u32(const void* p) {
    uint32_t a;
    asm("{ .reg .u64 t; cvta.to.shared.u64 t, %1; cvt.u32.u64 %0, t; }" : "=r"(a) : "l"(p));
    return a;
}
#define SWZ128(o) ((o) ^ (((o) >> 3) & 0x70))

__device__ __forceinline__ void ldmx4(uint32_t* r, uint32_t addr) {
    asm volatile("ldmatrix.sync.aligned.m8n8.x4.shared.b16 {%0,%1,%2,%3}, [%4];"
                 : "=r"(r[0]), "=r"(r[1]), "=r"(r[2]), "=r"(r[3]) : "r"(addr));
}
__device__ __forceinline__ void mma16816(float* d, const uint32_t* a,
                                         uint32_t b0, uint32_t b1) {
    asm volatile(
        "mma.sync.aligned.m16n8k16.row.col.f32.bf16.bf16.f32 "
        "{%0,%1,%2,%3}, {%4,%5,%6,%7}, {%8,%9}, {%0,%1,%2,%3};"
        : "+f"(d[0]), "+f"(d[1]), "+f"(d[2]), "+f"(d[3])
        : "r"(a[0]), "r"(a[1]), "r"(a[2]), "r"(a[3]), "r"(b0), "r"(b1));
}

// ---------------- scratch (device globals; no allocs) ----------------
__device__ float g_q[(size_t)Q_ * B_ * D_];
__device__ float g_kv[(size_t)KV_ * B_ * 2 * D_];
__device__ float g_pos[(size_t)192 * D_];
__device__ float g_attn[(size_t)Q_ * B_ * D_];
__device__ __nv_bfloat16 g_whi[1024 * 512];
__device__ __nv_bfloat16 g_wlo[1024 * 512];

// =====================================================================
// Weight split: hi = bf16(w), lo = bf16(w - hi)
// =====================================================================
__global__ void conv_w_kernel(const float* __restrict__ src, int n)
{
    int i = blockIdx.x * 256 + threadIdx.x;
    if (i < n) {
        float a = src[i];
        __nv_bfloat16 h = __float2bfloat16(a);
        g_whi[i] = h;
        g_wlo[i] = __float2bfloat16(a - __bfloat162float(h));
    }
}

// =====================================================================
// HMMA GEMM: C[m][n] = sum_k A[m][k] * W[n][k] (+bias)
// A fp32 (concat of <=3 row segments), W pre-split bf16 hi/lo.
// Split-precision: Ahi*Whi + Alo*Whi + Ahi*Wlo over 24 chunks of K=64.
// CTA tile 128x128, 8 warps (4x2), warp tile 32x64, double-buffered.
// =====================================================================
#define GSM_TOTAL 65536   // 2 x (16KB A + 16KB B)

__global__ __launch_bounds__(256) void gemm_tc_kernel(
    const float* __restrict__ A0, const float* __restrict__ A1,
    const float* __restrict__ A2, int r1, int r2,
    float* __restrict__ Cm, int Mr, int ldc,
    const float* __restrict__ bias)
{
    extern __shared__ char gsm[];
    const uint32_t sb = smem_u32(gsm);
    const int tid = threadIdx.x;
    const int wid = tid >> 5, lane = tid & 31;
    const int wm = wid & 3, wn = wid >> 2;
    const int row0 = blockIdx.y * 128, col0 = blockIdx.x * 128;

    // smem layout: A bufs at 0, 16384; B bufs at 32768, 49152
    float acc[2][8][4] = {};

    float4 pfa[8];
    uint4  pfb[4];

    // ---- prefetch lambda-equivalents (inline) ----
    auto prefetch = [&](int c) {
        const int seg = c >> 3;
        const int k0 = (c & 7) * 64;
        const __nv_bfloat16* wsrc = (seg == 2) ? g_wlo : g_whi;
        #pragma unroll
        for (int t = 0; t < 4; t++) {
            int gid = tid + t * 256;
            int ar = gid >> 3, g8 = gid & 7;
            int gr = row0 + ar;
            float4 f0 = {0,0,0,0}, f1 = {0,0,0,0};
            if (gr < Mr) {
                const float* src; int lr;
                if (gr < r1)      { src = A0; lr = gr; }
                else if (gr < r2) { src = A1; lr = gr - r1; }
                else              { src = A2; lr = gr - r2; }
                const float4* p = (const float4*)(src + (size_t)lr * 512 + k0 + g8 * 8);
                f0 = p[0]; f1 = p[1];
            }
            pfa[2 * t] = f0; pfa[2 * t + 1] = f1;
        }
        #pragma unroll
        for (int t = 0; t < 4; t++) {
            int gid = tid + t * 256;
            int br = gid >> 3, g8 = gid & 7;
            pfb[t] = *(const uint4*)(wsrc + (size_t)(col0 + br) * 512 + k0 + g8 * 8);
        }
    };
    auto store_smem = [&](int c, int bsel) {
        const bool want_alo = ((c >> 3) == 1);
        char* abuf = gsm + bsel * 16384;
        char* bbuf = gsm + 32768 + bsel * 16384;
        #pragma unroll
        for (int t = 0; t < 4; t++) {
            int gid = tid + t * 256;
            int ar = gid >> 3, g8 = gid & 7;
            float4 f0 = pfa[2 * t], f1 = pfa[2 * t + 1];
            float vv[8] = {f0.x, f0.y, f0.z, f0.w, f1.x, f1.y, f1.z, f1.w};
            uint32_t w[4];
            #pragma unroll
            for (int j = 0; j < 4; j++) {
                __nv_bfloat16 ha = __float2bfloat16(vv[2*j]);
                __nv_bfloat16 hb = __float2bfloat16(vv[2*j+1]);
                if (want_alo) {
                    ha = __float2bfloat16(vv[2*j]   - __bfloat162float(ha));
                    hb = __float2bfloat16(vv[2*j+1] - __bfloat162float(hb));
                }
                w[j] = (uint32_t)__bfloat16_as_ushort(ha)
                     | ((uint32_t)__bfloat16_as_ushort(hb) << 16);
            }
            uint32_t off = SWZ128((uint32_t)(ar * 128 + g8 * 16));
            *(uint4*)(abuf + off) = make_uint4(w[0], w[1], w[2], w[3]);
        }
        #pragma unroll
        for (int t = 0; t < 4; t++) {
            int gid = tid + t * 256;
            int br = gid >> 3, g8 = gid & 7;
            uint32_t off = SWZ128((uint32_t)(br * 128 + g8 * 16));
            *(uint4*)(bbuf + off) = pfb[t];
        }
    };

    prefetch(0);
    store_smem(0, 0);
    __syncthreads();

    for (int c = 0; c < 24; c++) {
        const int bsel = c & 1;
        if (c + 1 < 24) prefetch(c + 1);

        // ---- compute on buffer bsel ----
        const uint32_t Ab = sb + bsel * 16384;
        const uint32_t Bb = sb + 32768 + bsel * 16384;
        const int l15 = lane & 15, lh = lane >> 4;   // A addr pieces
        const int l8 = lane & 7, lg = lane >> 3;     // B addr pieces
        #pragma unroll
        for (int s = 0; s < 4; s++) {
            uint32_t afr[2][4];
            #pragma unroll
            for (int mt = 0; mt < 2; mt++) {
                int r = wm * 32 + mt * 16 + l15;
                uint32_t o = (uint32_t)(r * 128 + s * 32 + lh * 16);
                ldmx4(afr[mt], Ab + SWZ128(o));
            }
            uint32_t bfr[4][4];
            #pragma unroll
            for (int bt = 0; bt < 4; bt++) {
                int n = wn * 64 + bt * 16 + ((lg >> 1) ? 8 : 0) + l8;
                uint32_t o = (uint32_t)(n * 128 + s * 32 + (lg & 1) * 16);
                ldmx4(bfr[bt], Bb + SWZ128(o));
            }
            #pragma unroll
            for (int mt = 0; mt < 2; mt++)
                #pragma unroll
                for (int nt = 0; nt < 8; nt++) {
                    int bt = nt >> 1, sub = nt & 1;
                    mma16816(acc[mt][nt], afr[mt], bfr[bt][2*sub], bfr[bt][2*sub+1]);
                }
        }

        if (c + 1 < 24) store_smem(c + 1, bsel ^ 1);
        __syncthreads();
    }

    // ---- epilogue ----
    const int quad = lane >> 2, tq = lane & 3;
    #pragma unroll
    for (int mt = 0; mt < 2; mt++) {
        #pragma unroll
        for (int nt = 0; nt < 8; nt++) {
            int gr0 = row0 + wm * 32 + mt * 16 + quad;
            int gc  = col0 + wn * 64 + nt * 8 + tq * 2;
            float b0 = bias ? bias[gc]     : 0.f;
            float b1 = bias ? bias[gc + 1] : 0.f;
            if (gr0 < Mr) {
                float2 v = {acc[mt][nt][0] + b0, acc[mt][nt][1] + b1};
                *(float2*)&Cm[(size_t)gr0 * ldc + gc] = v;
            }
            if (gr0 + 8 < Mr) {
                float2 v = {acc[mt][nt][2] + b0, acc[mt][nt][3] + b1};
                *(float2*)&Cm[(size_t)(gr0 + 8) * ldc + gc] = v;
            }
        }
    }
}

// =====================================================================
// Fused compact attention (unchanged): one CTA per (chunk, bh)
// =====================================================================
__global__ __launch_bounds__(512) void fused_attn_kernel(
    const int* __restrict__ lengths,
    const float* __restrict__ pbu,
    const float* __restrict__ pbv)
{
    extern __shared__ float smf[];
    float* Qs      = smf;                 // 96 x 66
    float* Kt      = Qs + 96 * 66;        // 64 x 162
    float* Pt      = Kt + 64 * 162;       // 64 x 193
    float* Ss      = Pt + 64 * 193;       // 80 x 162
    float* Vt      = Ss + 80 * 162;       // 160 x 66
    float* bias_u  = Vt + 160 * 66;       // 160
    float* bias_vp = bias_u + 160;        // 192
    float* pbu_s   = bias_vp + 192;       // 64
    float* pbv_s   = pbu_s + 64;          // 64

    const int c = blockIdx.x, bh = blockIdx.y;
    const int b = bh >> 3, h = bh & 7;
    const int tid = threadIdx.x;
    const int ustart = (c == 0) ? 0 : (c - 1) * CL_;
    const int n_utt = (c == 0) ? 64 : 128;
    const int ncols = c + 4 + n_utt;
    const int len_b = lengths[b];

    for (int idx = tid; idx < 96 * 64; idx += 512) {
        int r = idx >> 6, k = idx & 63;
        float v = 0.f;
        if (r < 69) {
            int qrow = (r < 4) ? c * 4 + r
                     : (r < 68 ? R_ + c * 64 + (r - 4) : R_ + U_ + c);
            v = g_q[((size_t)qrow * B_ + b) * D_ + h * 64 + k];
        }
        Qs[r * 66 + k] = v;
    }
    for (int idx = tid; idx < 160 * 64; idx += 512) {
        int i = idx >> 6, k = idx & 63;
        float v = 0.f;
        if (i < ncols) {
            int kvrow = (i < c) ? i
                      : (i < c + 4 ? M_ + c * 4 + (i - c)
                                   : M_ + R_ + ustart + (i - c - 4));
            v = g_kv[((size_t)kvrow * B_ + b) * (2 * D_) + h * 64 + k];
        }
        Kt[k * 162 + i] = v;
    }
    for (int idx = tid; idx < 191 * 64; idx += 512) {
        int pl = idx >> 6, k = idx & 63;
        Pt[k * 193 + pl] = g_pos[(size_t)pl * D_ + h * 64 + k];
    }
    for (int idx = tid; idx < ncols * 64; idx += 512) {
        int i = idx >> 6, k = idx & 63;
        int kvrow = (i < c) ? i
                  : (i < c + 4 ? M_ + c * 4 + (i - c)
                               : M_ + R_ + ustart + (i - c - 4));
        Vt[i * 66 + k] = g_kv[((size_t)kvrow * B_ + b) * (2 * D_) + D_ + h * 64 + k];
    }
    if (tid < 64) pbu_s[tid] = pbu[h * 64 + tid];
    else if (tid < 128) pbv_s[tid - 64] = pbv[h * 64 + tid - 64];
    __syncthreads();

    if (tid < 160) {
        float s = 0.f;
        if (tid < ncols) {
            #pragma unroll 8
            for (int k = 0; k < 64; k++) s += pbu_s[k] * Kt[k * 162 + tid];
        }
        bias_u[tid] = s;
    } else if (tid < 160 + 191) {
        int pl = tid - 160;
        float s = 0.f;
        #pragma unroll 8
        for (int k = 0; k < 64; k++) s += pbv_s[k] * Pt[k * 193 + pl];
        bias_vp[pl] = s;
    }
    __syncthreads();

    const int ty = tid >> 4, tx = tid & 15;

    {   // C1: AC
        u64t acc2[3][5] = {};
        for (int kk = 0; kk < 64; kk++) {
            u64t aa[3];
            #pragma unroll
            for (int a = 0; a < 3; a++) aa[a] = pk2(Qs[(ty + 32 * a) * 66 + kk]);
            u64t bv[5];
            #pragma unroll
            for (int j = 0; j < 5; j++)
                bv[j] = *reinterpret_cast<const u64t*>(&Kt[kk * 162 + 2 * tx + 32 * j]);
            #pragma unroll
            for (int a = 0; a < 3; a++)
                #pragma unroll
                for (int j = 0; j < 5; j++)
                    fma2(acc2[a][j], aa[a], bv[j]);
        }
        #pragma unroll
        for (int a = 0; a < 3; a++) {
            int r = ty + 32 * a;
            if (r < 80) {
                #pragma unroll
                for (int j = 0; j < 5; j++) {
                    int colp = 2 * tx + 32 * j;
                    u64t s = add2(acc2[a][j], *reinterpret_cast<const u64t*>(&bias_u[colp]));
                    *reinterpret_cast<u64t*>(&Ss[r * 162 + colp]) = s;
                }
            }
        }
    }
    __syncthreads();

    {   // C2: banded BD
        const int pbase = (c == 0) ? 127 : 63;
        const int plb = pbase - ty + tx - 32;
        float accb[2][8] = {};
        for (int kk = 0; kk < 64; kk++) {
            float qv[2];
            #pragma unroll
            for (int a = 0; a < 2; a++) qv[a] = Qs[(4 + ty + 32 * a) * 66 + kk];
            float pv[10];
            #pragma unroll
            for (int t = 0; t < 10; t++) {
                int pl = plb + 16 * t;
                pl = (pl < 0) ? 0 : (pl > 190 ? 190 : pl);
                pv[t] = Pt[kk * 193 + pl];
            }
            #pragma unroll
            for (int a = 0; a < 2; a++)
                #pragma unroll
                for (int bb = 0; bb < 8; bb++)
                    accb[a][bb] += qv[a] * pv[bb - 2 * a + 2];
        }
        #pragma unroll
        for (int a = 0; a < 2; a++) {
            int u = ty + 32 * a;
            #pragma unroll
            for (int bb = 0; bb < 8; bb++) {
                int j = tx + 16 * bb;
                if (j < n_utt) {
                    int pl = pbase - u + j;
                    Ss[(4 + u) * 162 + (c + 4 + j)] += accb[a][bb] + bias_vp[pl];
                }
            }
        }
    }
    __syncthreads();

    {   // softmax
        const int warp = tid >> 5, lane = tid & 31;
        const int limit_j = len_b - ustart;
        const int uc0 = c + 4;
        for (int r = warp; r < 69; r += 16) {
            float vals[5];
            float mx = -3.4e38f;
            #pragma unroll
            for (int g = 0; g < 5; g++) {
                int i = lane + 32 * g;
                float v = -3.4e38f;
                if (i < ncols) {
                    v = Ss[r * 162 + i] * SCALING_;
                    if (i >= uc0 && (i - uc0) >= limit_j) v = NEG_INF_;
                }
                vals[g] = v;
                mx = fmaxf(mx, v);
            }
            #pragma unroll
            for (int o = 16; o > 0; o >>= 1) mx = fmaxf(mx, __shfl_xor_sync(~0u, mx, o));
            float sum = 0.f;
            #pragma unroll
            for (int g = 0; g < 5; g++) {
                float e = __expf(vals[g] - mx);
                vals[g] = e;
                sum += e;
            }
            #pragma unroll
            for (int o = 16; o > 0; o >>= 1) sum += __shfl_xor_sync(~0u, sum, o);
            float inv = 1.f / sum;
            #pragma unroll
            for (int g = 0; g < 5; g++) {
                int i = lane + 32 * g;
                if (i < ncols) Ss[r * 162 + i] = vals[g] * inv;
            }
        }
    }
    __syncthreads();

    {   // PV
        u64t acc2[3][2] = {};
        int rofs[3];
        #pragma unroll
        for (int a = 0; a < 3; a++) {
            int rr = ty + 32 * a; if (rr > 79) rr = 79;
            rofs[a] = rr * 162;
        }
        for (int i = 0; i < ncols; i++) {
            u64t ssv[3];
            #pragma unroll
            for (int a = 0; a < 3; a++) ssv[a] = pk2(Ss[rofs[a] + i]);
            u64t vv[2];
            #pragma unroll
            for (int dd = 0; dd < 2; dd++)
                vv[dd] = *reinterpret_cast<const u64t*>(&Vt[i * 66 + 2 * tx + 32 * dd]);
            #pragma unroll
            for (int a = 0; a < 3; a++)
                #pragma unroll
                for (int dd = 0; dd < 2; dd++)
                    fma2(acc2[a][dd], ssv[a], vv[dd]);
        }
        #pragma unroll
        for (int a = 0; a < 3; a++) {
            int r = ty + 32 * a;
            if (r < 69) {
                int qrow = (r < 4) ? c * 4 + r
                         : (r < 68 ? R_ + c * 64 + (r - 4) : R_ + U_ + c);
                float* dst = g_attn + ((size_t)qrow * B_ + b) * D_ + h * 64 + 2 * tx;
                #pragma unroll
                for (int dd = 0; dd < 2; dd++) {
                    float2 v = upk(acc2[a][dd]);
                    *reinterpret_cast<float2*>(dst + 32 * dd) = v;
                }
            }
        }
    }
}

// ---------------- out_mem = clip(attn[R+U:], -10, 10) ----------------
__global__ void clip_kernel(float* __restrict__ out)
{
    const size_t off = (size_t)(R_ + U_) * B_ * D_;
    int i = blockIdx.x * 256 + threadIdx.x;
    float v = g_attn[off + i];
    out[off + i] = fminf(10.f, fmaxf(-10.f, v));
}

// ---------------- launch ----------------
extern "C" void kernel_launch(void* const* d_in, const int* in_sizes, int n_in,
                              void* d_out, int out_size)
{
    const float* utt    = (const float*)d_in[0];
    const int*   lens   = (const int*)  d_in[1];
    const float* rc     = (const float*)d_in[2];
    const float* summ   = (const float*)d_in[3];
    const float* mem    = (const float*)d_in[4];
    const float* pos_e  = (const float*)d_in[6];
    const float* W_kv   = (const float*)d_in[7];
    const float* b_kv   = (const float*)d_in[8];
    const float* W_q    = (const float*)d_in[9];
    const float* b_q    = (const float*)d_in[10];
    const float* W_out  = (const float*)d_in[11];
    const float* b_out  = (const float*)d_in[12];
    const float* W_pos  = (const float*)d_in[13];
    const float* pbu    = (const float*)d_in[14];
    const float* pbv    = (const float*)d_in[15];
    float* out = (float*)d_out;

    float *q_buf, *kv_buf, *pos_buf, *attn_buf;
    cudaGetSymbolAddress((void**)&q_buf,    g_q);
    cudaGetSymbolAddress((void**)&kv_buf,   g_kv);
    cudaGetSymbolAddress((void**)&pos_buf,  g_pos);
    cudaGetSymbolAddress((void**)&attn_buf, g_attn);

    const size_t SMEM_ATTN =
        (size_t)(96*66 + 64*162 + 64*193 + 80*162 + 160*66 + 160 + 192 + 64 + 64) * 4;
    cudaFuncSetAttribute(fused_attn_kernel,
                         cudaFuncAttributeMaxDynamicSharedMemorySize, (int)SMEM_ATTN);
    cudaFuncSetAttribute(gemm_tc_kernel,
                         cudaFuncAttributeMaxDynamicSharedMemorySize, GSM_TOTAL);

    const dim3 blk(256);
    const float* pos_src = pos_e + (size_t)(U_ - 128) * D_;

    // ---- Q projection: [rc(512), utt(8192), summ(128)] x W_q ----
    conv_w_kernel<<<dim3(1024), blk>>>(W_q, 512 * 512);
    gemm_tc_kernel<<<dim3(4, 69), blk, GSM_TOTAL>>>(rc, utt, summ, 512, 8704,
                                                    q_buf, Q_ * B_, D_, b_q);
    // ---- KV projection: [mem(120), rc(512), utt(8192)] x W_kv ----
    conv_w_kernel<<<dim3(2048), blk>>>(W_kv, 1024 * 512);
    gemm_tc_kernel<<<dim3(8, 69), blk, GSM_TOTAL>>>(mem, rc, utt, 120, 632,
                                                    kv_buf, KV_ * B_, 2 * D_, b_kv);
    // ---- pos projection (191 rows) ----
    conv_w_kernel<<<dim3(1024), blk>>>(W_pos, 512 * 512);
    gemm_tc_kernel<<<dim3(4, 2), blk, GSM_TOTAL>>>(pos_src, pos_src, pos_src, 191, 191,
                                                   pos_buf, 191, D_, nullptr);
    // ---- fused attention ----
    fused_attn_kernel<<<dim3(C_, 64), dim3(512), SMEM_ATTN>>>(lens, pbu, pbv);

    // ---- output projection ----
    conv_w_kernel<<<dim3(1024), blk>>>(W_out, 512 * 512);
    gemm_tc_kernel<<<dim3(4, 68), blk, GSM_TOTAL>>>(attn_buf, attn_buf, attn_buf,
                                                    (R_ + U_) * B_, (R_ + U_) * B_,
                                                    out, (R_ + U_) * B_, D_, b_out);
    clip_kernel<<<dim3(256), blk>>>(out);
}

// round 6
// speedup vs baseline: 5.9060x; 1.4457x over previous
#include <cuda_runtime.h>
#include <cuda_bf16.h>
#include <cstddef>
#include <cstdint>

// ---------------- problem constants ----------------
#define U_  1024
#define B_  8
#define D_  512
#define H_  8
#define HD_ 64
#define CL_ 64
#define RC_ 4
#define C_  16
#define R_  64
#define S_  16
#define M_  15
#define Q_  1104
#define KV_ 1103
#define NEG_INF_ (-100000000.0f)
#define SCALING_ 0.125f

// ---------------- packed f32x2 helpers ----------------
typedef unsigned long long u64t;
__device__ __forceinline__ u64t pk2(float v) {
    u64t r; asm("mov.b64 %0, {%1, %1};" : "=l"(r) : "f"(v)); return r;
}
__device__ __forceinline__ void fma2(u64t& d, u64t a, u64t b) {
    asm("fma.rn.f32x2 %0, %1, %2, %0;" : "+l"(d) : "l"(a), "l"(b));
}
__device__ __forceinline__ u64t add2(u64t a, u64t b) {
    u64t r; asm("add.rn.f32x2 %0, %1, %2;" : "=l"(r) : "l"(a), "l"(b)); return r;
}
__device__ __forceinline__ float2 upk(u64t v) {
    float2 f; asm("mov.b64 {%0, %1}, %2;" : "=f"(f.x), "=f"(f.y) : "l"(v)); return f;
}

// ---------------- mma / async helpers ----------------
__device__ __forceinline__ uint32_t smem_u32(const void* p) {
    uint32_t a;
    asm("{ .reg .u64 t; cvta.to.shared.u64 t, %1; cvt.u32.u64 %0, t; }" : "=r"(a) : "l"(p));
    return a;
}
#define SWZ128(o) ((o) ^ (((o) >> 3) & 0x70))

__device__ __forceinline__ void ldmx4(uint32_t* r, uint32_t addr) {
    asm volatile("ldmatrix.sync.aligned.m8n8.x4.shared.b16 {%0,%1,%2,%3}, [%4];"
                 : "=r"(r[0]), "=r"(r[1]), "=r"(r[2]), "=r"(r[3]) : "r"(addr));
}
__device__ __forceinline__ void mma16816(float* d, const uint32_t* a,
                                         uint32_t b0, uint32_t b1) {
    asm volatile(
        "mma.sync.aligned.m16n8k16.row.col.f32.bf16.bf16.f32 "
        "{%0,%1,%2,%3}, {%4,%5,%6,%7}, {%8,%9}, {%0,%1,%2,%3};"
        : "+f"(d[0]), "+f"(d[1]), "+f"(d[2]), "+f"(d[3])
        : "r"(a[0]), "r"(a[1]), "r"(a[2]), "r"(a[3]), "r"(b0), "r"(b1));
}
__device__ __forceinline__ void cpa16(uint32_t dst, const void* src) {
    asm volatile("cp.async.cg.shared.global [%0], [%1], 16;" :: "r"(dst), "l"(src));
}
#define CPA_COMMIT() asm volatile("cp.async.commit_group;" ::: "memory")
#define CPA_WAIT1()  asm volatile("cp.async.wait_group 1;" ::: "memory")
#define CPA_WAIT0()  asm volatile("cp.async.wait_group 0;" ::: "memory")

// ---------------- scratch (device globals; no allocs) ----------------
__device__ float g_q[(size_t)Q_ * B_ * D_];
__device__ float g_kv[(size_t)KV_ * B_ * 2 * D_];
__device__ float g_pos[(size_t)192 * D_];
__device__ float g_attn[(size_t)Q_ * B_ * D_];
__device__ __nv_bfloat16 g_whi[1024 * 512];
__device__ __nv_bfloat16 g_wlo[1024 * 512];
// A concat buffer: rows [mem 0-119 | rc 120-631 | utt 632-8823 | summ 8824-8951 | pos 8952-9142]
__device__ __nv_bfloat16 g_ahi[(size_t)9216 * 512];
__device__ __nv_bfloat16 g_alo[(size_t)9216 * 512];

// =====================================================================
// Weight split: hi = bf16(w), lo = bf16(w - hi)
// =====================================================================
__global__ void conv_w_kernel(const float* __restrict__ src, int n)
{
    int i = blockIdx.x * 256 + threadIdx.x;
    if (i < n) {
        float a = src[i];
        __nv_bfloat16 h = __float2bfloat16(a);
        g_whi[i] = h;
        g_wlo[i] = __float2bfloat16(a - __bfloat162float(h));
    }
}

// =====================================================================
// A split: concat of <=4 row segments -> g_ahi/g_alo at dst_row0
// =====================================================================
__global__ void conv_a_kernel(const float* __restrict__ A0, const float* __restrict__ A1,
                              const float* __restrict__ A2, const float* __restrict__ A3,
                              int r1, int r2, int r3, int nrows, int dst_row0)
{
    int i = blockIdx.x * 256 + threadIdx.x;
    if (i >= nrows * 128) return;
    int row = i >> 7, c4 = (i & 127) * 4;
    const float* src; int lr;
    if (row < r1)      { src = A0; lr = row; }
    else if (row < r2) { src = A1; lr = row - r1; }
    else if (row < r3) { src = A2; lr = row - r2; }
    else               { src = A3; lr = row - r3; }
    float4 v = *(const float4*)(src + (size_t)lr * 512 + c4);
    float vv[4] = {v.x, v.y, v.z, v.w};
    ushort hi[4], lo[4];
    #pragma unroll
    for (int j = 0; j < 4; j++) {
        __nv_bfloat16 h = __float2bfloat16(vv[j]);
        __nv_bfloat16 l = __float2bfloat16(vv[j] - __bfloat162float(h));
        hi[j] = __bfloat16_as_ushort(h);
        lo[j] = __bfloat16_as_ushort(l);
    }
    size_t o = (size_t)(dst_row0 + row) * 512 + c4;
    *(uint2*)&g_ahi[o] = make_uint2((uint32_t)hi[0] | ((uint32_t)hi[1] << 16),
                                    (uint32_t)hi[2] | ((uint32_t)hi[3] << 16));
    *(uint2*)&g_alo[o] = make_uint2((uint32_t)lo[0] | ((uint32_t)lo[1] << 16),
                                    (uint32_t)lo[2] | ((uint32_t)lo[3] << 16));
}

// =====================================================================
// HMMA GEMM with cp.async 3-stage pipeline.
// C[m][n] = sum over 24 chunks: seg0 Ahi*Whi, seg1 Alo*Whi, seg2 Ahi*Wlo.
// CTA tile 128x128, 8 warps (4x2), 2 CTAs/SM.
// smem: A stages [0,48K), B stages [48K,96K)
// =====================================================================
#define GSM_TOTAL 98304

__global__ __launch_bounds__(256, 2) void gemm_tc_kernel(
    const __nv_bfloat16* __restrict__ Ahi, const __nv_bfloat16* __restrict__ Alo,
    float* __restrict__ Cm, int Mr, int ldc, const float* __restrict__ bias)
{
    extern __shared__ char gsm[];
    const uint32_t sb = smem_u32(gsm);
    const int tid = threadIdx.x;
    const int wid = tid >> 5, lane = tid & 31;
    const int wm = wid & 3, wn = wid >> 2;
    const int row0 = blockIdx.y * 128, col0 = blockIdx.x * 128;

    // per-thread copy coords
    const int car = tid >> 3, cg8 = tid & 7;

    auto issue = [&](int c) {
        const int seg = c >> 3;
        const int k0 = (c & 7) * 64;
        const __nv_bfloat16* asrc = (seg == 1) ? Alo : Ahi;
        const __nv_bfloat16* wsrc = (seg == 2) ? g_wlo : g_whi;
        char* abuf = gsm + (c % 3) * 16384;
        char* bbuf = gsm + 49152 + (c % 3) * 16384;
        #pragma unroll
        for (int t = 0; t < 4; t++) {
            int ar = car + t * 32;
            int gr = row0 + ar; if (gr >= Mr) gr = Mr - 1;
            cpa16(smem_u32(abuf) + SWZ128((uint32_t)(ar * 128 + cg8 * 16)),
                  asrc + (size_t)gr * 512 + k0 + cg8 * 8);
        }
        #pragma unroll
        for (int t = 0; t < 4; t++) {
            int br = car + t * 32;
            cpa16(smem_u32(bbuf) + SWZ128((uint32_t)(br * 128 + cg8 * 16)),
                  wsrc + (size_t)(col0 + br) * 512 + k0 + cg8 * 8);
        }
        CPA_COMMIT();
    };

    float acc[2][8][4] = {};

    issue(0);
    issue(1);

    const int l15 = lane & 15, lh = lane >> 4;
    const int l8 = lane & 7, lg = lane >> 3;

    for (int c = 0; c < 24; c++) {
        if (c < 23) CPA_WAIT1(); else CPA_WAIT0();
        __syncthreads();

        const uint32_t Ab = sb + (c % 3) * 16384;
        const uint32_t Bb = sb + 49152 + (c % 3) * 16384;
        #pragma unroll
        for (int s = 0; s < 4; s++) {
            uint32_t afr[2][4];
            #pragma unroll
            for (int mt = 0; mt < 2; mt++) {
                int r = wm * 32 + mt * 16 + l15;
                uint32_t o = (uint32_t)(r * 128 + s * 32 + lh * 16);
                ldmx4(afr[mt], Ab + SWZ128(o));
            }
            uint32_t bfr[4][4];
            #pragma unroll
            for (int bt = 0; bt < 4; bt++) {
                int n = wn * 64 + bt * 16 + ((lg >> 1) ? 8 : 0) + l8;
                uint32_t o = (uint32_t)(n * 128 + s * 32 + (lg & 1) * 16);
                ldmx4(bfr[bt], Bb + SWZ128(o));
            }
            #pragma unroll
            for (int mt = 0; mt < 2; mt++)
                #pragma unroll
                for (int nt = 0; nt < 8; nt++) {
                    int bt = nt >> 1, sub = nt & 1;
                    mma16816(acc[mt][nt], afr[mt], bfr[bt][2*sub], bfr[bt][2*sub+1]);
                }
        }
        if (c + 2 < 24) issue(c + 2);
    }

    // ---- epilogue ----
    const int quad = lane >> 2, tq = lane & 3;
    #pragma unroll
    for (int mt = 0; mt < 2; mt++) {
        #pragma unroll
        for (int nt = 0; nt < 8; nt++) {
            int gr0 = row0 + wm * 32 + mt * 16 + quad;
            int gc  = col0 + wn * 64 + nt * 8 + tq * 2;
            float b0 = bias ? bias[gc]     : 0.f;
            float b1 = bias ? bias[gc + 1] : 0.f;
            if (gr0 < Mr) {
                float2 v = {acc[mt][nt][0] + b0, acc[mt][nt][1] + b1};
                *(float2*)&Cm[(size_t)gr0 * ldc + gc] = v;
            }
            if (gr0 + 8 < Mr) {
                float2 v = {acc[mt][nt][2] + b0, acc[mt][nt][3] + b1};
                *(float2*)&Cm[(size_t)(gr0 + 8) * ldc + gc] = v;
            }
        }
    }
}

// =====================================================================
// Fused compact attention (unchanged): one CTA per (chunk, bh)
// =====================================================================
__global__ __launch_bounds__(512) void fused_attn_kernel(
    const int* __restrict__ lengths,
    const float* __restrict__ pbu,
    const float* __restrict__ pbv)
{
    extern __shared__ float smf[];
    float* Qs      = smf;                 // 96 x 66
    float* Kt      = Qs + 96 * 66;        // 64 x 162
    float* Pt      = Kt + 64 * 162;       // 64 x 193
    float* Ss      = Pt + 64 * 193;       // 80 x 162
    float* Vt      = Ss + 80 * 162;       // 160 x 66
    float* bias_u  = Vt + 160 * 66;       // 160
    float* bias_vp = bias_u + 160;        // 192
    float* pbu_s   = bias_vp + 192;       // 64
    float* pbv_s   = pbu_s + 64;          // 64

    const int c = blockIdx.x, bh = blockIdx.y;
    const int b = bh >> 3, h = bh & 7;
    const int tid = threadIdx.x;
    const int ustart = (c == 0) ? 0 : (c - 1) * CL_;
    const int n_utt = (c == 0) ? 64 : 128;
    const int ncols = c + 4 + n_utt;
    const int len_b = lengths[b];

    for (int idx = tid; idx < 96 * 64; idx += 512) {
        int r = idx >> 6, k = idx & 63;
        float v = 0.f;
        if (r < 69) {
            int qrow = (r < 4) ? c * 4 + r
                     : (r < 68 ? R_ + c * 64 + (r - 4) : R_ + U_ + c);
            v = g_q[((size_t)qrow * B_ + b) * D_ + h * 64 + k];
        }
        Qs[r * 66 + k] = v;
    }
    for (int idx = tid; idx < 160 * 64; idx += 512) {
        int i = idx >> 6, k = idx & 63;
        float v = 0.f;
        if (i < ncols) {
            int kvrow = (i < c) ? i
                      : (i < c + 4 ? M_ + c * 4 + (i - c)
                                   : M_ + R_ + ustart + (i - c - 4));
            v = g_kv[((size_t)kvrow * B_ + b) * (2 * D_) + h * 64 + k];
        }
        Kt[k * 162 + i] = v;
    }
    for (int idx = tid; idx < 191 * 64; idx += 512) {
        int pl = idx >> 6, k = idx & 63;
        Pt[k * 193 + pl] = g_pos[(size_t)pl * D_ + h * 64 + k];
    }
    for (int idx = tid; idx < ncols * 64; idx += 512) {
        int i = idx >> 6, k = idx & 63;
        int kvrow = (i < c) ? i
                  : (i < c + 4 ? M_ + c * 4 + (i - c)
                               : M_ + R_ + ustart + (i - c - 4));
        Vt[i * 66 + k] = g_kv[((size_t)kvrow * B_ + b) * (2 * D_) + D_ + h * 64 + k];
    }
    if (tid < 64) pbu_s[tid] = pbu[h * 64 + tid];
    else if (tid < 128) pbv_s[tid - 64] = pbv[h * 64 + tid - 64];
    __syncthreads();

    if (tid < 160) {
        float s = 0.f;
        if (tid < ncols) {
            #pragma unroll 8
            for (int k = 0; k < 64; k++) s += pbu_s[k] * Kt[k * 162 + tid];
        }
        bias_u[tid] = s;
    } else if (tid < 160 + 191) {
        int pl = tid - 160;
        float s = 0.f;
        #pragma unroll 8
        for (int k = 0; k < 64; k++) s += pbv_s[k] * Pt[k * 193 + pl];
        bias_vp[pl] = s;
    }
    __syncthreads();

    const int ty = tid >> 4, tx = tid & 15;

    {   // C1: AC
        u64t acc2[3][5] = {};
        for (int kk = 0; kk < 64; kk++) {
            u64t aa[3];
            #pragma unroll
            for (int a = 0; a < 3; a++) aa[a] = pk2(Qs[(ty + 32 * a) * 66 + kk]);
            u64t bv[5];
            #pragma unroll
            for (int j = 0; j < 5; j++)
                bv[j] = *reinterpret_cast<const u64t*>(&Kt[kk * 162 + 2 * tx + 32 * j]);
            #pragma unroll
            for (int a = 0; a < 3; a++)
                #pragma unroll
                for (int j = 0; j < 5; j++)
                    fma2(acc2[a][j], aa[a], bv[j]);
        }
        #pragma unroll
        for (int a = 0; a < 3; a++) {
            int r = ty + 32 * a;
            if (r < 80) {
                #pragma unroll
                for (int j = 0; j < 5; j++) {
                    int colp = 2 * tx + 32 * j;
                    u64t s = add2(acc2[a][j], *reinterpret_cast<const u64t*>(&bias_u[colp]));
                    *reinterpret_cast<u64t*>(&Ss[r * 162 + colp]) = s;
                }
            }
        }
    }
    __syncthreads();

    {   // C2: banded BD
        const int pbase = (c == 0) ? 127 : 63;
        const int plb = pbase - ty + tx - 32;
        float accb[2][8] = {};
        for (int kk = 0; kk < 64; kk++) {
            float qv[2];
            #pragma unroll
            for (int a = 0; a < 2; a++) qv[a] = Qs[(4 + ty + 32 * a) * 66 + kk];
            float pv[10];
            #pragma unroll
            for (int t = 0; t < 10; t++) {
                int pl = plb + 16 * t;
                pl = (pl < 0) ? 0 : (pl > 190 ? 190 : pl);
                pv[t] = Pt[kk * 193 + pl];
            }
            #pragma unroll
            for (int a = 0; a < 2; a++)
                #pragma unroll
                for (int bb = 0; bb < 8; bb++)
                    accb[a][bb] += qv[a] * pv[bb - 2 * a + 2];
        }
        #pragma unroll
        for (int a = 0; a < 2; a++) {
            int u = ty + 32 * a;
            #pragma unroll
            for (int bb = 0; bb < 8; bb++) {
                int j = tx + 16 * bb;
                if (j < n_utt) {
                    int pl = pbase - u + j;
                    Ss[(4 + u) * 162 + (c + 4 + j)] += accb[a][bb] + bias_vp[pl];
                }
            }
        }
    }
    __syncthreads();

    {   // softmax
        const int warp = tid >> 5, lane = tid & 31;
        const int limit_j = len_b - ustart;
        const int uc0 = c + 4;
        for (int r = warp; r < 69; r += 16) {
            float vals[5];
            float mx = -3.4e38f;
            #pragma unroll
            for (int g = 0; g < 5; g++) {
                int i = lane + 32 * g;
                float v = -3.4e38f;
                if (i < ncols) {
                    v = Ss[r * 162 + i] * SCALING_;
                    if (i >= uc0 && (i - uc0) >= limit_j) v = NEG_INF_;
                }
                vals[g] = v;
                mx = fmaxf(mx, v);
            }
            #pragma unroll
            for (int o = 16; o > 0; o >>= 1) mx = fmaxf(mx, __shfl_xor_sync(~0u, mx, o));
            float sum = 0.f;
            #pragma unroll
            for (int g = 0; g < 5; g++) {
                float e = __expf(vals[g] - mx);
                vals[g] = e;
                sum += e;
            }
            #pragma unroll
            for (int o = 16; o > 0; o >>= 1) sum += __shfl_xor_sync(~0u, sum, o);
            float inv = 1.f / sum;
            #pragma unroll
            for (int g = 0; g < 5; g++) {
                int i = lane + 32 * g;
                if (i < ncols) Ss[r * 162 + i] = vals[g] * inv;
            }
        }
    }
    __syncthreads();

    {   // PV
        u64t acc2[3][2] = {};
        int rofs[3];
        #pragma unroll
        for (int a = 0; a < 3; a++) {
            int rr = ty + 32 * a; if (rr > 79) rr = 79;
            rofs[a] = rr * 162;
        }
        for (int i = 0; i < ncols; i++) {
            u64t ssv[3];
            #pragma unroll
            for (int a = 0; a < 3; a++) ssv[a] = pk2(Ss[rofs[a] + i]);
            u64t vv[2];
            #pragma unroll
            for (int dd = 0; dd < 2; dd++)
                vv[dd] = *reinterpret_cast<const u64t*>(&Vt[i * 66 + 2 * tx + 32 * dd]);
            #pragma unroll
            for (int a = 0; a < 3; a++)
                #pragma unroll
                for (int dd = 0; dd < 2; dd++)
                    fma2(acc2[a][dd], ssv[a], vv[dd]);
        }
        #pragma unroll
        for (int a = 0; a < 3; a++) {
            int r = ty + 32 * a;
            if (r < 69) {
                int qrow = (r < 4) ? c * 4 + r
                         : (r < 68 ? R_ + c * 64 + (r - 4) : R_ + U_ + c);
                float* dst = g_attn + ((size_t)qrow * B_ + b) * D_ + h * 64 + 2 * tx;
                #pragma unroll
                for (int dd = 0; dd < 2; dd++) {
                    float2 v = upk(acc2[a][dd]);
                    *reinterpret_cast<float2*>(dst + 32 * dd) = v;
                }
            }
        }
    }
}

// ---------------- out_mem = clip(attn[R+U:], -10, 10) ----------------
__global__ void clip_kernel(float* __restrict__ out)
{
    const size_t off = (size_t)(R_ + U_) * B_ * D_;
    int i = blockIdx.x * 256 + threadIdx.x;
    float v = g_attn[off + i];
    out[off + i] = fminf(10.f, fmaxf(-10.f, v));
}

// ---------------- launch ----------------
extern "C" void kernel_launch(void* const* d_in, const int* in_sizes, int n_in,
                              void* d_out, int out_size)
{
    const float* utt    = (const float*)d_in[0];
    const int*   lens   = (const int*)  d_in[1];
    const float* rc     = (const float*)d_in[2];
    const float* summ   = (const float*)d_in[3];
    const float* mem    = (const float*)d_in[4];
    const float* pos_e  = (const float*)d_in[6];
    const float* W_kv   = (const float*)d_in[7];
    const float* b_kv   = (const float*)d_in[8];
    const float* W_q    = (const float*)d_in[9];
    const float* b_q    = (const float*)d_in[10];
    const float* W_out  = (const float*)d_in[11];
    const float* b_out  = (const float*)d_in[12];
    const float* W_pos  = (const float*)d_in[13];
    const float* pbu    = (const float*)d_in[14];
    const float* pbv    = (const float*)d_in[15];
    float* out = (float*)d_out;

    float *q_buf, *kv_buf, *pos_buf, *attn_buf;
    __nv_bfloat16 *ahi, *alo;
    cudaGetSymbolAddress((void**)&q_buf,    g_q);
    cudaGetSymbolAddress((void**)&kv_buf,   g_kv);
    cudaGetSymbolAddress((void**)&pos_buf,  g_pos);
    cudaGetSymbolAddress((void**)&attn_buf, g_attn);
    cudaGetSymbolAddress((void**)&ahi,      g_ahi);
    cudaGetSymbolAddress((void**)&alo,      g_alo);

    const size_t SMEM_ATTN =
        (size_t)(96*66 + 64*162 + 64*193 + 80*162 + 160*66 + 160 + 192 + 64 + 64) * 4;
    cudaFuncSetAttribute(fused_attn_kernel,
                         cudaFuncAttributeMaxDynamicSharedMemorySize, (int)SMEM_ATTN);
    cudaFuncSetAttribute(gemm_tc_kernel,
                         cudaFuncAttributeMaxDynamicSharedMemorySize, GSM_TOTAL);

    const dim3 blk(256);
    const float* pos_src = pos_e + (size_t)(U_ - 128) * D_;

    // ---- A conversion: concat [mem|rc|utt|summ] (8952 rows) + pos (191 rows) ----
    conv_a_kernel<<<dim3((8952 * 128 + 255) / 256), blk>>>(
        mem, rc, utt, summ, 120, 632, 8824, 8952, 0);
    conv_a_kernel<<<dim3((191 * 128 + 255) / 256), blk>>>(
        pos_src, pos_src, pos_src, pos_src, 191, 191, 191, 191, 8952);

    // ---- Q projection: rows 120..8951 of concat (rc,utt,summ) ----
    conv_w_kernel<<<dim3(1024), blk>>>(W_q, 512 * 512);
    gemm_tc_kernel<<<dim3(4, 69), blk, GSM_TOTAL>>>(
        ahi + (size_t)120 * 512, alo + (size_t)120 * 512, q_buf, Q_ * B_, D_, b_q);

    // ---- KV projection: rows 0..8823 (mem,rc,utt) ----
    conv_w_kernel<<<dim3(2048), blk>>>(W_kv, 1024 * 512);
    gemm_tc_kernel<<<dim3(8, 69), blk, GSM_TOTAL>>>(
        ahi, alo, kv_buf, KV_ * B_, 2 * D_, b_kv);

    // ---- pos projection: rows 8952..9142 ----
    conv_w_kernel<<<dim3(1024), blk>>>(W_pos, 512 * 512);
    gemm_tc_kernel<<<dim3(4, 2), blk, GSM_TOTAL>>>(
        ahi + (size_t)8952 * 512, alo + (size_t)8952 * 512, pos_buf, 191, D_, nullptr);

    // ---- fused attention ----
    fused_attn_kernel<<<dim3(C_, 64), dim3(512), SMEM_ATTN>>>(lens, pbu, pbv);

    // ---- output projection: attn rows 0..8703 ----
    conv_a_kernel<<<dim3((8704 * 128 + 255) / 256), blk>>>(
        attn_buf, attn_buf, attn_buf, attn_buf, 8704, 8704, 8704, 8704, 0);
    conv_w_kernel<<<dim3(1024), blk>>>(W_out, 512 * 512);
    gemm_tc_kernel<<<dim3(4, 68), blk, GSM_TOTAL>>>(
        ahi, alo, out, (R_ + U_) * B_, D_, b_out);
    clip_kernel<<<dim3(256), blk>>>(out);
}

// round 7
// speedup vs baseline: 6.2851x; 1.0642x over previous
#include <cuda_runtime.h>
#include <cuda_bf16.h>
#include <cstddef>
#include <cstdint>

// ---------------- problem constants ----------------
#define U_  1024
#define B_  8
#define D_  512
#define H_  8
#define HD_ 64
#define CL_ 64
#define RC_ 4
#define C_  16
#define R_  64
#define S_  16
#define M_  15
#define Q_  1104
#define KV_ 1103
#define NEG_INF_ (-100000000.0f)
#define SCALING_ 0.125f

// ---------------- packed f32x2 helpers ----------------
typedef unsigned long long u64t;
__device__ __forceinline__ u64t pk2(float v) {
    u64t r; asm("mov.b64 %0, {%1, %1};" : "=l"(r) : "f"(v)); return r;
}
__device__ __forceinline__ void fma2(u64t& d, u64t a, u64t b) {
    asm("fma.rn.f32x2 %0, %1, %2, %0;" : "+l"(d) : "l"(a), "l"(b));
}
__device__ __forceinline__ u64t add2(u64t a, u64t b) {
    u64t r; asm("add.rn.f32x2 %0, %1, %2;" : "=l"(r) : "l"(a), "l"(b)); return r;
}
__device__ __forceinline__ float2 upk(u64t v) {
    float2 f; asm("mov.b64 {%0, %1}, %2;" : "=f"(f.x), "=f"(f.y) : "l"(v)); return f;
}

// ---------------- mma / async helpers ----------------
__device__ __forceinline__ uint32_t smem_u32(const void* p) {
    uint32_t a;
    asm("{ .reg .u64 t; cvta.to.shared.u64 t, %1; cvt.u32.u64 %0, t; }" : "=r"(a) : "l"(p));
    return a;
}
#define SWZ128(o) ((o) ^ (((o) >> 3) & 0x70))

__device__ __forceinline__ void ldmx4(uint32_t* r, uint32_t addr) {
    asm volatile("ldmatrix.sync.aligned.m8n8.x4.shared.b16 {%0,%1,%2,%3}, [%4];"
                 : "=r"(r[0]), "=r"(r[1]), "=r"(r[2]), "=r"(r[3]) : "r"(addr));
}
__device__ __forceinline__ void mma16816(float* d, const uint32_t* a,
                                         uint32_t b0, uint32_t b1) {
    asm volatile(
        "mma.sync.aligned.m16n8k16.row.col.f32.bf16.bf16.f32 "
        "{%0,%1,%2,%3}, {%4,%5,%6,%7}, {%8,%9}, {%0,%1,%2,%3};"
        : "+f"(d[0]), "+f"(d[1]), "+f"(d[2]), "+f"(d[3])
        : "r"(a[0]), "r"(a[1]), "r"(a[2]), "r"(a[3]), "r"(b0), "r"(b1));
}
__device__ __forceinline__ void cpa16(uint32_t dst, const void* src) {
    asm volatile("cp.async.cg.shared.global [%0], [%1], 16;" :: "r"(dst), "l"(src));
}
#define CPA_COMMIT() asm volatile("cp.async.commit_group;" ::: "memory")
#define CPA_WAIT1()  asm volatile("cp.async.wait_group 1;" ::: "memory")
#define CPA_WAIT0()  asm volatile("cp.async.wait_group 0;" ::: "memory")

// ---------------- scratch (device globals; no allocs) ----------------
__device__ float g_q[(size_t)Q_ * B_ * D_];
__device__ float g_kv[(size_t)KV_ * B_ * 2 * D_];
__device__ float g_pos[(size_t)192 * D_];
__device__ float g_attn[(size_t)Q_ * B_ * D_];
__device__ float g_bd[(size_t)64 * 1024 * 128];       // banded BD scores per bh
__device__ __nv_bfloat16 g_whi[1024 * 512];
__device__ __nv_bfloat16 g_wlo[1024 * 512];
__device__ __nv_bfloat16 g_ahi[(size_t)9216 * 512];
__device__ __nv_bfloat16 g_alo[(size_t)9216 * 512];

// =====================================================================
// Weight split
// =====================================================================
__global__ void conv_w_kernel(const float* __restrict__ src, int n)
{
    int i = blockIdx.x * 256 + threadIdx.x;
    if (i < n) {
        float a = src[i];
        __nv_bfloat16 h = __float2bfloat16(a);
        g_whi[i] = h;
        g_wlo[i] = __float2bfloat16(a - __bfloat162float(h));
    }
}

// =====================================================================
// A split (concat of <=4 row segments)
// =====================================================================
__global__ void conv_a_kernel(const float* __restrict__ A0, const float* __restrict__ A1,
                              const float* __restrict__ A2, const float* __restrict__ A3,
                              int r1, int r2, int r3, int nrows, int dst_row0)
{
    int i = blockIdx.x * 256 + threadIdx.x;
    if (i >= nrows * 128) return;
    int row = i >> 7, c4 = (i & 127) * 4;
    const float* src; int lr;
    if (row < r1)      { src = A0; lr = row; }
    else if (row < r2) { src = A1; lr = row - r1; }
    else if (row < r3) { src = A2; lr = row - r2; }
    else               { src = A3; lr = row - r3; }
    float4 v = *(const float4*)(src + (size_t)lr * 512 + c4);
    float vv[4] = {v.x, v.y, v.z, v.w};
    ushort hi[4], lo[4];
    #pragma unroll
    for (int j = 0; j < 4; j++) {
        __nv_bfloat16 h = __float2bfloat16(vv[j]);
        __nv_bfloat16 l = __float2bfloat16(vv[j] - __bfloat162float(h));
        hi[j] = __bfloat16_as_ushort(h);
        lo[j] = __bfloat16_as_ushort(l);
    }
    size_t o = (size_t)(dst_row0 + row) * 512 + c4;
    *(uint2*)&g_ahi[o] = make_uint2((uint32_t)hi[0] | ((uint32_t)hi[1] << 16),
                                    (uint32_t)hi[2] | ((uint32_t)hi[3] << 16));
    *(uint2*)&g_alo[o] = make_uint2((uint32_t)lo[0] | ((uint32_t)lo[1] << 16),
                                    (uint32_t)lo[2] | ((uint32_t)lo[3] << 16));
}

// =====================================================================
// HMMA GEMM with cp.async 3-stage pipeline (unchanged from R6)
// =====================================================================
#define GSM_TOTAL 98304

__global__ __launch_bounds__(256, 2) void gemm_tc_kernel(
    const __nv_bfloat16* __restrict__ Ahi, const __nv_bfloat16* __restrict__ Alo,
    float* __restrict__ Cm, int Mr, int ldc, const float* __restrict__ bias)
{
    extern __shared__ char gsm[];
    const uint32_t sb = smem_u32(gsm);
    const int tid = threadIdx.x;
    const int wid = tid >> 5, lane = tid & 31;
    const int wm = wid & 3, wn = wid >> 2;
    const int row0 = blockIdx.y * 128, col0 = blockIdx.x * 128;
    const int car = tid >> 3, cg8 = tid & 7;

    auto issue = [&](int c) {
        const int seg = c >> 3;
        const int k0 = (c & 7) * 64;
        const __nv_bfloat16* asrc = (seg == 1) ? Alo : Ahi;
        const __nv_bfloat16* wsrc = (seg == 2) ? g_wlo : g_whi;
        char* abuf = gsm + (c % 3) * 16384;
        char* bbuf = gsm + 49152 + (c % 3) * 16384;
        #pragma unroll
        for (int t = 0; t < 4; t++) {
            int ar = car + t * 32;
            int gr = row0 + ar; if (gr >= Mr) gr = Mr - 1;
            cpa16(smem_u32(abuf) + SWZ128((uint32_t)(ar * 128 + cg8 * 16)),
                  asrc + (size_t)gr * 512 + k0 + cg8 * 8);
        }
        #pragma unroll
        for (int t = 0; t < 4; t++) {
            int br = car + t * 32;
            cpa16(smem_u32(bbuf) + SWZ128((uint32_t)(br * 128 + cg8 * 16)),
                  wsrc + (size_t)(col0 + br) * 512 + k0 + cg8 * 8);
        }
        CPA_COMMIT();
    };

    float acc[2][8][4] = {};
    issue(0);
    issue(1);

    const int l15 = lane & 15, lh = lane >> 4;
    const int l8 = lane & 7, lg = lane >> 3;

    for (int c = 0; c < 24; c++) {
        if (c < 23) CPA_WAIT1(); else CPA_WAIT0();
        __syncthreads();
        const uint32_t Ab = sb + (c % 3) * 16384;
        const uint32_t Bb = sb + 49152 + (c % 3) * 16384;
        #pragma unroll
        for (int s = 0; s < 4; s++) {
            uint32_t afr[2][4];
            #pragma unroll
            for (int mt = 0; mt < 2; mt++) {
                int r = wm * 32 + mt * 16 + l15;
                uint32_t o = (uint32_t)(r * 128 + s * 32 + lh * 16);
                ldmx4(afr[mt], Ab + SWZ128(o));
            }
            uint32_t bfr[4][4];
            #pragma unroll
            for (int bt = 0; bt < 4; bt++) {
                int n = wn * 64 + bt * 16 + ((lg >> 1) ? 8 : 0) + l8;
                uint32_t o = (uint32_t)(n * 128 + s * 32 + (lg & 1) * 16);
                ldmx4(bfr[bt], Bb + SWZ128(o));
            }
            #pragma unroll
            for (int mt = 0; mt < 2; mt++)
                #pragma unroll
                for (int nt = 0; nt < 8; nt++) {
                    int bt = nt >> 1, sub = nt & 1;
                    mma16816(acc[mt][nt], afr[mt], bfr[bt][2*sub], bfr[bt][2*sub+1]);
                }
        }
        if (c + 2 < 24) issue(c + 2);
    }

    const int quad = lane >> 2, tq = lane & 3;
    #pragma unroll
    for (int mt = 0; mt < 2; mt++) {
        #pragma unroll
        for (int nt = 0; nt < 8; nt++) {
            int gr0 = row0 + wm * 32 + mt * 16 + quad;
            int gc  = col0 + wn * 64 + nt * 8 + tq * 2;
            float b0 = bias ? bias[gc]     : 0.f;
            float b1 = bias ? bias[gc + 1] : 0.f;
            if (gr0 < Mr) {
                float2 v = {acc[mt][nt][0] + b0, acc[mt][nt][1] + b1};
                *(float2*)&Cm[(size_t)gr0 * ldc + gc] = v;
            }
            if (gr0 + 8 < Mr) {
                float2 v = {acc[mt][nt][2] + b0, acc[mt][nt][3] + b1};
                *(float2*)&Cm[(size_t)(gr0 + 8) * ldc + gc] = v;
            }
        }
    }
}

// =====================================================================
// BD kernel: banded qv.pos (+pbv.pos bias) -> g_bd[bh][1024 u][128 j]
// grid (16 chunks, 64 bh), 256 threads, ~67KB smem -> 3 CTAs/SM
// =====================================================================
#define BDSM_FLOATS (64*65 + 64*193 + 192 + 64)   // 16768 floats

__global__ __launch_bounds__(256) void bd_kernel(const float* __restrict__ pbv)
{
    extern __shared__ float smf[];
    float* qv      = smf;                    // 64 x 65
    float* Pt      = smf + 64 * 65;          // 64 x 193 [k][pl]
    float* bias_vp = Pt + 64 * 193;          // 192
    float* pbv_s   = bias_vp + 192;          // 64

    const int c = blockIdx.x, bh = blockIdx.y;
    const int b = bh >> 3, h = bh & 7;
    const int tid = threadIdx.x;
    const int pbase = (c == 0) ? 127 : 63;

    for (int idx = tid; idx < 64 * 64; idx += 256) {
        int u = idx >> 6, k = idx & 63;
        qv[u * 65 + k] = g_q[((size_t)(R_ + c * 64 + u) * B_ + b) * D_ + h * 64 + k];
    }
    for (int idx = tid; idx < 191 * 64; idx += 256) {
        int pl = idx >> 6, k = idx & 63;
        Pt[k * 193 + pl] = g_pos[(size_t)pl * D_ + h * 64 + k];
    }
    if (tid < 64) pbv_s[tid] = pbv[h * 64 + tid];
    __syncthreads();

    if (tid < 191) {
        float s = 0.f;
        #pragma unroll 8
        for (int k = 0; k < 64; k++) s += pbv_s[k] * Pt[k * 193 + tid];
        bias_vp[tid] = s;
    }
    __syncthreads();

    const int ty = tid >> 4, tx = tid & 15;
    const int plb = pbase - ty + tx;
    float accb[4][8] = {};
    for (int kk = 0; kk < 64; kk++) {
        float qq[4];
        #pragma unroll
        for (int a = 0; a < 4; a++) qq[a] = qv[(ty + 16 * a) * 65 + kk];
        float pv[11];
        #pragma unroll
        for (int t = 0; t < 11; t++) {
            int pl = plb + 16 * (t - 3);
            pl = (pl < 0) ? 0 : (pl > 190 ? 190 : pl);
            pv[t] = Pt[kk * 193 + pl];
        }
        #pragma unroll
        for (int a = 0; a < 4; a++)
            #pragma unroll
            for (int bb = 0; bb < 8; bb++)
                accb[a][bb] += qq[a] * pv[bb - a + 3];
    }
    float* dst = g_bd + ((size_t)bh * 1024 + c * 64) * 128;
    #pragma unroll
    for (int a = 0; a < 4; a++) {
        int u = ty + 16 * a;
        #pragma unroll
        for (int bb = 0; bb < 8; bb++) {
            int j = tx + 16 * bb;
            int pl = pbase - u + j;
            pl = (pl < 0) ? 0 : (pl > 190 ? 190 : pl);
            dst[(size_t)u * 128 + j] = accb[a][bb] + bias_vp[pl];
        }
    }
}

// =====================================================================
// Fused attention v2: AC + softmax(+BD from gmem) + PV.
// ~105KB smem -> 2 CTAs/SM, 512 threads.
// =====================================================================
#define AT_QS  0            // 80 x 65
#define AT_KT  5200         // 64 x 162   (later V: 160 x 64)
#define AT_SS  15568        // 69 x 162
#define AT_BU  26746        // 160
#define AT_PBU 26906        // 64
#define AT_FLOATS 26970

__global__ __launch_bounds__(512, 2) void fused_attn_kernel(
    const int* __restrict__ lengths,
    const float* __restrict__ pbu)
{
    extern __shared__ float smf[];
    float* Qs     = smf + AT_QS;
    float* Kt     = smf + AT_KT;
    float* Ss     = smf + AT_SS;
    float* bias_u = smf + AT_BU;
    float* pbu_s  = smf + AT_PBU;

    const int c = blockIdx.x, bh = blockIdx.y;
    const int b = bh >> 3, h = bh & 7;
    const int tid = threadIdx.x;
    const int ustart = (c == 0) ? 0 : (c - 1) * CL_;
    const int n_utt = (c == 0) ? 64 : 128;
    const int ncols = c + 4 + n_utt;
    const int len_b = lengths[b];

    // ---- load Q (80 rows, >=69 zero) ----
    for (int idx = tid; idx < 80 * 64; idx += 512) {
        int r = idx >> 6, k = idx & 63;
        float v = 0.f;
        if (r < 69) {
            int qrow = (r < 4) ? c * 4 + r
                     : (r < 68 ? R_ + c * 64 + (r - 4) : R_ + U_ + c);
            v = g_q[((size_t)qrow * B_ + b) * D_ + h * 64 + k];
        }
        Qs[r * 65 + k] = v;
    }
    // ---- load K transposed [k][i] ----
    for (int idx = tid; idx < 160 * 64; idx += 512) {
        int i = idx >> 6, k = idx & 63;
        float v = 0.f;
        if (i < ncols) {
            int kvrow = (i < c) ? i
                      : (i < c + 4 ? M_ + c * 4 + (i - c)
                                   : M_ + R_ + ustart + (i - c - 4));
            v = g_kv[((size_t)kvrow * B_ + b) * (2 * D_) + h * 64 + k];
        }
        Kt[k * 162 + i] = v;
    }
    if (tid < 64) pbu_s[tid] = pbu[h * 64 + tid];
    __syncthreads();

    // ---- bias_u[i] = pbu . K_i ----
    if (tid < 160) {
        float s = 0.f;
        if (tid < ncols) {
            #pragma unroll 8
            for (int k = 0; k < 64; k++) s += pbu_s[k] * Kt[k * 162 + tid];
        }
        bias_u[tid] = s;
    }
    __syncthreads();

    const int ty = tid >> 4, tx = tid & 15;

    // ---- C1: AC scores ----
    {
        int qofs[3];
        #pragma unroll
        for (int a = 0; a < 3; a++) {
            int r = ty + 32 * a; if (r > 79) r = 79;
            qofs[a] = r * 65;
        }
        u64t acc2[3][5] = {};
        for (int kk = 0; kk < 64; kk++) {
            u64t aa[3];
            #pragma unroll
            for (int a = 0; a < 3; a++) aa[a] = pk2(Qs[qofs[a] + kk]);
            u64t bv[5];
            #pragma unroll
            for (int j = 0; j < 5; j++)
                bv[j] = *reinterpret_cast<const u64t*>(&Kt[kk * 162 + 2 * tx + 32 * j]);
            #pragma unroll
            for (int a = 0; a < 3; a++)
                #pragma unroll
                for (int j = 0; j < 5; j++)
                    fma2(acc2[a][j], aa[a], bv[j]);
        }
        #pragma unroll
        for (int a = 0; a < 3; a++) {
            int r = ty + 32 * a;
            if (r < 69) {
                #pragma unroll
                for (int j = 0; j < 5; j++) {
                    int colp = 2 * tx + 32 * j;
                    u64t s = add2(acc2[a][j], *reinterpret_cast<const u64t*>(&bias_u[colp]));
                    *reinterpret_cast<u64t*>(&Ss[r * 162 + colp]) = s;
                }
            }
        }
    }
    __syncthreads();

    // ---- V load into Kt region (stride 64) ----
    float* Vt = Kt;
    for (int idx = tid; idx < ncols * 64; idx += 512) {
        int i = idx >> 6, k = idx & 63;
        int kvrow = (i < c) ? i
                  : (i < c + 4 ? M_ + c * 4 + (i - c)
                               : M_ + R_ + ustart + (i - c - 4));
        Vt[i * 64 + k] = g_kv[((size_t)kvrow * B_ + b) * (2 * D_) + D_ + h * 64 + k];
    }

    // ---- softmax (scale + BD + masks) ----
    {
        const int warp = tid >> 5, lane = tid & 31;
        const int limit_j = len_b - ustart;
        const int uc0 = c + 4;
        for (int r = warp; r < 69; r += 16) {
            const bool is_utt = (r >= 4) && (r < 68);
            const float* bd = g_bd + ((size_t)bh * 1024 + c * 64 + (r - 4)) * 128;
            float vals[5];
            float mx = -3.4e38f;
            #pragma unroll
            for (int g = 0; g < 5; g++) {
                int i = lane + 32 * g;
                float v = -3.4e38f;
                if (i < ncols) {
                    float s = Ss[r * 162 + i];
                    if (i >= uc0) {
                        int j = i - uc0;
                        if (is_utt) s += bd[j];
                        v = (j >= limit_j) ? NEG_INF_ : s * SCALING_;
                    } else {
                        v = s * SCALING_;
                    }
                }
                vals[g] = v;
                mx = fmaxf(mx, v);
            }
            #pragma unroll
            for (int o = 16; o > 0; o >>= 1) mx = fmaxf(mx, __shfl_xor_sync(~0u, mx, o));
            float sum = 0.f;
            #pragma unroll
            for (int g = 0; g < 5; g++) {
                float e = __expf(vals[g] - mx);
                vals[g] = e;
                sum += e;
            }
            #pragma unroll
            for (int o = 16; o > 0; o >>= 1) sum += __shfl_xor_sync(~0u, sum, o);
            float inv = 1.f / sum;
            #pragma unroll
            for (int g = 0; g < 5; g++) {
                int i = lane + 32 * g;
                if (i < ncols) Ss[r * 162 + i] = vals[g] * inv;
            }
        }
    }
    __syncthreads();

    // ---- PV ----
    {
        u64t acc2[3][2] = {};
        int rofs[3];
        #pragma unroll
        for (int a = 0; a < 3; a++) {
            int rr = ty + 32 * a; if (rr > 68) rr = 68;
            rofs[a] = rr * 162;
        }
        for (int i = 0; i < ncols; i++) {
            u64t ssv[3];
            #pragma unroll
            for (int a = 0; a < 3; a++) ssv[a] = pk2(Ss[rofs[a] + i]);
            u64t vv[2];
            #pragma unroll
            for (int dd = 0; dd < 2; dd++)
                vv[dd] = *reinterpret_cast<const u64t*>(&Vt[i * 64 + 2 * tx + 32 * dd]);
            #pragma unroll
            for (int a = 0; a < 3; a++)
                #pragma unroll
                for (int dd = 0; dd < 2; dd++)
                    fma2(acc2[a][dd], ssv[a], vv[dd]);
        }
        #pragma unroll
        for (int a = 0; a < 3; a++) {
            int r = ty + 32 * a;
            if (r < 69) {
                int qrow = (r < 4) ? c * 4 + r
                         : (r < 68 ? R_ + c * 64 + (r - 4) : R_ + U_ + c);
                float* dst = g_attn + ((size_t)qrow * B_ + b) * D_ + h * 64 + 2 * tx;
                #pragma unroll
                for (int dd = 0; dd < 2; dd++) {
                    float2 v = upk(acc2[a][dd]);
                    *reinterpret_cast<float2*>(dst + 32 * dd) = v;
                }
            }
        }
    }
}

// ---------------- out_mem = clip(attn[R+U:], -10, 10) ----------------
__global__ void clip_kernel(float* __restrict__ out)
{
    const size_t off = (size_t)(R_ + U_) * B_ * D_;
    int i = blockIdx.x * 256 + threadIdx.x;
    float v = g_attn[off + i];
    out[off + i] = fminf(10.f, fmaxf(-10.f, v));
}

// ---------------- launch ----------------
extern "C" void kernel_launch(void* const* d_in, const int* in_sizes, int n_in,
                              void* d_out, int out_size)
{
    const float* utt    = (const float*)d_in[0];
    const int*   lens   = (const int*)  d_in[1];
    const float* rc     = (const float*)d_in[2];
    const float* summ   = (const float*)d_in[3];
    const float* mem    = (const float*)d_in[4];
    const float* pos_e  = (const float*)d_in[6];
    const float* W_kv   = (const float*)d_in[7];
    const float* b_kv   = (const float*)d_in[8];
    const float* W_q    = (const float*)d_in[9];
    const float* b_q    = (const float*)d_in[10];
    const float* W_out  = (const float*)d_in[11];
    const float* b_out  = (const float*)d_in[12];
    const float* W_pos  = (const float*)d_in[13];
    const float* pbu    = (const float*)d_in[14];
    const float* pbv    = (const float*)d_in[15];
    float* out = (float*)d_out;

    float *q_buf, *kv_buf, *pos_buf, *attn_buf;
    __nv_bfloat16 *ahi, *alo;
    cudaGetSymbolAddress((void**)&q_buf,    g_q);
    cudaGetSymbolAddress((void**)&kv_buf,   g_kv);
    cudaGetSymbolAddress((void**)&pos_buf,  g_pos);
    cudaGetSymbolAddress((void**)&attn_buf, g_attn);
    cudaGetSymbolAddress((void**)&ahi,      g_ahi);
    cudaGetSymbolAddress((void**)&alo,      g_alo);

    const size_t SMEM_ATTN = (size_t)AT_FLOATS * 4;
    const size_t SMEM_BD   = (size_t)BDSM_FLOATS * 4;
    cudaFuncSetAttribute(fused_attn_kernel,
                         cudaFuncAttributeMaxDynamicSharedMemorySize, (int)SMEM_ATTN);
    cudaFuncSetAttribute(bd_kernel,
                         cudaFuncAttributeMaxDynamicSharedMemorySize, (int)SMEM_BD);
    cudaFuncSetAttribute(gemm_tc_kernel,
                         cudaFuncAttributeMaxDynamicSharedMemorySize, GSM_TOTAL);

    const dim3 blk(256);
    const float* pos_src = pos_e + (size_t)(U_ - 128) * D_;

    // ---- A conversion: concat [mem|rc|utt|summ] + pos rows ----
    conv_a_kernel<<<dim3((8952 * 128 + 255) / 256), blk>>>(
        mem, rc, utt, summ, 120, 632, 8824, 8952, 0);
    conv_a_kernel<<<dim3((191 * 128 + 255) / 256), blk>>>(
        pos_src, pos_src, pos_src, pos_src, 191, 191, 191, 191, 8952);

    // ---- projections ----
    conv_w_kernel<<<dim3(1024), blk>>>(W_q, 512 * 512);
    gemm_tc_kernel<<<dim3(4, 69), blk, GSM_TOTAL>>>(
        ahi + (size_t)120 * 512, alo + (size_t)120 * 512, q_buf, Q_ * B_, D_, b_q);

    conv_w_kernel<<<dim3(2048), blk>>>(W_kv, 1024 * 512);
    gemm_tc_kernel<<<dim3(8, 69), blk, GSM_TOTAL>>>(
        ahi, alo, kv_buf, KV_ * B_, 2 * D_, b_kv);

    conv_w_kernel<<<dim3(1024), blk>>>(W_pos, 512 * 512);
    gemm_tc_kernel<<<dim3(4, 2), blk, GSM_TOTAL>>>(
        ahi + (size_t)8952 * 512, alo + (size_t)8952 * 512, pos_buf, 191, D_, nullptr);

    // ---- BD precompute + fused attention ----
    bd_kernel<<<dim3(C_, 64), blk, SMEM_BD>>>(pbv);
    fused_attn_kernel<<<dim3(C_, 64), dim3(512), SMEM_ATTN>>>(lens, pbu);

    // ---- output projection ----
    conv_a_kernel<<<dim3((8704 * 128 + 255) / 256), blk>>>(
        attn_buf, attn_buf, attn_buf, attn_buf, 8704, 8704, 8704, 8704, 0);
    conv_w_kernel<<<dim3(1024), blk>>>(W_out, 512 * 512);
    gemm_tc_kernel<<<dim3(4, 68), blk, GSM_TOTAL>>>(
        ahi, alo, out, (R_ + U_) * B_, D_, b_out);
    clip_kernel<<<dim3(256), blk>>>(out);
}